// round 10
// baseline (speedup 1.0000x reference)
#include <cuda_runtime.h>
#include <cuda_fp16.h>
#include <math.h>
#include <stdint.h>

#define B_SZ  2
#define S_LEN 2048
#define D_DIM 1024
#define H_NUM 16
#define DKH   64
#define MTOT  (B_SZ * S_LEN)          // 4096

// ---------------------------------------------------------------------------
// Scratch (allocation-free rule: __device__ globals). fp16 operands.
// ---------------------------------------------------------------------------
__device__ __half g_aQh[MTOT * D_DIM], g_aQl[MTOT * D_DIM];  // split(query)
__device__ __half g_aKh[MTOT * D_DIM], g_aKl[MTOT * D_DIM];  // split(key)
__device__ __half g_aVh[MTOT * D_DIM], g_aVl[MTOT * D_DIM];  // split(value)
__device__ __half g_wq[D_DIM * D_DIM], g_wk[D_DIM * D_DIM];  // weights fp16
__device__ __half g_wv[D_DIM * D_DIM], g_wo[D_DIM * D_DIM];
__device__ __half g_Qh[MTOT * D_DIM], g_Ql[MTOT * D_DIM];    // Q proj (split)
__device__ __half g_Kv[MTOT * D_DIM];                        // K proj (single)
__device__ __half g_Vv[MTOT * D_DIM];                        // V proj (single)
__device__ __half g_Xh[MTOT * D_DIM], g_Xl[MTOT * D_DIM];    // attn out (split)

// ===========================================================================
// helpers
// ===========================================================================
__device__ __forceinline__ uint32_t smem_u32(const void* p) {
    uint32_t a;
    asm("{ .reg .u64 t; cvta.to.shared.u64 t, %1; cvt.u32.u64 %0, t; }"
        : "=r"(a) : "l"(p));
    return a;
}
__device__ __forceinline__ void ldmx4(uint32_t* r, uint32_t addr) {
    asm volatile("ldmatrix.sync.aligned.m8n8.x4.shared.b16 {%0,%1,%2,%3}, [%4];"
                 : "=r"(r[0]), "=r"(r[1]), "=r"(r[2]), "=r"(r[3]) : "r"(addr));
}
__device__ __forceinline__ void ldmx4t(uint32_t* r, uint32_t addr) {
    asm volatile("ldmatrix.sync.aligned.m8n8.x4.trans.shared.b16 {%0,%1,%2,%3}, [%4];"
                 : "=r"(r[0]), "=r"(r[1]), "=r"(r[2]), "=r"(r[3]) : "r"(addr));
}
__device__ __forceinline__ void mma16816(float* c, const uint32_t* a,
                                         uint32_t b0, uint32_t b1) {
    asm volatile(
        "mma.sync.aligned.m16n8k16.row.col.f32.f16.f16.f32 "
        "{%0,%1,%2,%3}, {%4,%5,%6,%7}, {%8,%9}, {%0,%1,%2,%3};"
        : "+f"(c[0]), "+f"(c[1]), "+f"(c[2]), "+f"(c[3])
        : "r"(a[0]), "r"(a[1]), "r"(a[2]), "r"(a[3]), "r"(b0), "r"(b1));
}
__device__ __forceinline__ uint32_t packh(float x, float y) {
    __half2 h = __float22half2_rn(make_float2(x, y));
    return *(uint32_t*)&h;
}
__device__ __forceinline__ void split2h(float x, float y, uint32_t& h, uint32_t& l) {
    h = packh(x, y);
    __half2 t = *(__half2*)&h;
    float2 f = __half22float2(t);
    l = packh(x - f.x, y - f.y);
}
__device__ __forceinline__ void cpasync16(uint32_t dst, const void* src) {
    asm volatile("cp.async.cg.shared.global [%0], [%1], 16;"
                 :: "r"(dst), "l"(src));
}
__device__ __forceinline__ void cp_commit() {
    asm volatile("cp.async.commit_group;" ::: "memory");
}
__device__ __forceinline__ void cp_wait0() {
    asm volatile("cp.async.wait_group 0;" ::: "memory");
}
__device__ __forceinline__ void cp_wait1() {
    asm volatile("cp.async.wait_group 1;" ::: "memory");
}

// ===========================================================================
// convert_all: z=0..2 split activations, z=3..6 convert weights (grid-stride)
// ===========================================================================
__global__ void convert_all(const float4* __restrict__ q, const float4* __restrict__ k,
                            const float4* __restrict__ v,
                            const float4* __restrict__ wq, const float4* __restrict__ wk,
                            const float4* __restrict__ wv, const float4* __restrict__ wo,
                            uint2* __restrict__ aqh, uint2* __restrict__ aql,
                            uint2* __restrict__ akh, uint2* __restrict__ akl,
                            uint2* __restrict__ avh, uint2* __restrict__ avl,
                            uint2* __restrict__ owq, uint2* __restrict__ owk,
                            uint2* __restrict__ owv, uint2* __restrict__ owo)
{
    const int z = blockIdx.z;
    const int stride = gridDim.x * blockDim.x;
    if (z < 3) {
        const float4* src = (z == 0) ? q : (z == 1) ? k : v;
        uint2* hi = (z == 0) ? aqh : (z == 1) ? akh : avh;
        uint2* lo = (z == 0) ? aql : (z == 1) ? akl : avl;
        const int n4 = MTOT * D_DIM / 4;
        for (int i = blockIdx.x * blockDim.x + threadIdx.x; i < n4; i += stride) {
            const float4 w = src[i];
            uint2 uh, ul;
            split2h(w.x, w.y, uh.x, ul.x);
            split2h(w.z, w.w, uh.y, ul.y);
            hi[i] = uh;
            lo[i] = ul;
        }
    } else {
        const float4* src = (z == 3) ? wq : (z == 4) ? wk : (z == 5) ? wv : wo;
        uint2* dst = (z == 3) ? owq : (z == 4) ? owk : (z == 5) ? owv : owo;
        const int n4 = D_DIM * D_DIM / 4;
        for (int i = blockIdx.x * blockDim.x + threadIdx.x; i < n4; i += stride) {
            const float4 w = src[i];
            dst[i] = make_uint2(packh(w.x, w.y), packh(w.z, w.w));
        }
    }
}

// ===========================================================================
// GEMM geometry: CTA tile 256(m) x 128(n), 512 threads = 16 warps (8m x 2n),
// warp tile 32x64 (acc 2x8 m16n8). K staged 64 fp16, cp.async double-buffer.
// ===========================================================================
constexpr int SASB   = 144;                // padded row bytes (64 fp16 + pad)
constexpr int AT     = 256 * SASB;         // 36864: one 256-row A tile
constexpr int BT     = 128 * SASB;         // 18432: one 128-row B tile
constexpr int GSTAGE = 2 * AT + BT;        // 92160 per stage (Ahi, Alo, B)
constexpr int SM_GEMM_TOTAL = 2 * GSTAGE;  // 184320
constexpr int STAGES = D_DIM / 64;         // 16

__device__ __forceinline__ void gemm_stage_compute(
    uint32_t bufb, int warp_m, int warp_n, int lr, int lkb, float acc[2][8][4])
{
#pragma unroll
    for (int ks = 0; ks < 4; ks++) {
        const uint32_t kb = ks * 32 + lkb;
        uint32_t ah[2][4], al[2][4];
#pragma unroll
        for (int mi = 0; mi < 2; mi++) {
            const uint32_t byte = (warp_m * 32 + mi * 16 + lr) * SASB + kb;
            ldmx4(ah[mi], bufb + byte);
            ldmx4(al[mi], bufb + AT + byte);
        }
        uint32_t bh[8][2];
#pragma unroll
        for (int nb = 0; nb < 4; nb++) {
            const uint32_t byte = (warp_n * 64 + nb * 16 + lr) * SASB + kb;
            uint32_t r[4];
            ldmx4(r, bufb + 2 * AT + byte);
            bh[nb * 2][0] = r[0]; bh[nb * 2 + 1][0] = r[1];
            bh[nb * 2][1] = r[2]; bh[nb * 2 + 1][1] = r[3];
        }
#pragma unroll
        for (int mi = 0; mi < 2; mi++)
#pragma unroll
            for (int ni = 0; ni < 8; ni++) {
                mma16816(acc[mi][ni], ah[mi], bh[ni][0], bh[ni][1]);
                mma16816(acc[mi][ni], al[mi], bh[ni][0], bh[ni][1]);
            }
    }
}

// producer: 10 cp.async per thread per stage (Ahi 2048 + Alo 2048 + B 1024 chunks)
__device__ __forceinline__ void gemm_produce(
    uint32_t sb, int s, const __half* Ahb, const __half* Alb, const __half* Bb,
    int tid)
{
    const uint32_t bufb = sb + (s & 1) * GSTAGE;
#pragma unroll
    for (int i = 0; i < 10; i++) {
        const int c = i * 512 + tid;
        if (c < 2048) {
            const int row = c >> 3, ch = c & 7;
            cpasync16(bufb + row * SASB + ch * 16,
                      Ahb + (size_t)row * D_DIM + s * 64 + ch * 8);
        } else if (c < 4096) {
            const int row = (c - 2048) >> 3, ch = c & 7;
            cpasync16(bufb + AT + row * SASB + ch * 16,
                      Alb + (size_t)row * D_DIM + s * 64 + ch * 8);
        } else {
            const int row = (c - 4096) >> 3, ch = c & 7;
            cpasync16(bufb + 2 * AT + row * SASB + ch * 16,
                      Bb + (size_t)row * D_DIM + s * 64 + ch * 8);
        }
    }
}

// ===========================================================================
// gemm_proj: z=0: Q (split out), z=1: K (single), z=2: V (single).
// ===========================================================================
__global__ __launch_bounds__(512, 1)
void gemm_proj(const __half* __restrict__ aQh, const __half* __restrict__ aQl,
               const __half* __restrict__ aKh, const __half* __restrict__ aKl,
               const __half* __restrict__ aVh, const __half* __restrict__ aVl,
               const __half* __restrict__ wq, const __half* __restrict__ wk,
               const __half* __restrict__ wv,
               __half* __restrict__ Qh, __half* __restrict__ Ql,
               __half* __restrict__ Kv, __half* __restrict__ Vv)
{
    extern __shared__ char smc[];
    const uint32_t sb = smem_u32(smc);
    const int tid  = threadIdx.x;
    const int wid  = tid >> 5;
    const int lane = tid & 31;
    const int warp_m = wid & 7;
    const int warp_n = wid >> 3;
    const int m0 = blockIdx.y * 256;
    const int n0 = blockIdx.x * 128;
    const int z  = blockIdx.z;
    const int N  = D_DIM;

    const __half* Ahb = ((z == 0) ? aQh : (z == 1) ? aKh : aVh) + (size_t)m0 * D_DIM;
    const __half* Alb = ((z == 0) ? aQl : (z == 1) ? aKl : aVl) + (size_t)m0 * D_DIM;
    const __half* Bb  = ((z == 0) ? wq  : (z == 1) ? wk  : wv)  + (size_t)n0 * D_DIM;

    float acc[2][8][4];
#pragma unroll
    for (int mi = 0; mi < 2; mi++)
#pragma unroll
        for (int ni = 0; ni < 8; ni++)
#pragma unroll
            for (int q = 0; q < 4; q++) acc[mi][ni][q] = 0.f;

    const int lr  = lane & 15;
    const int lkb = (lane >> 4) << 4;

    gemm_produce(sb, 0, Ahb, Alb, Bb, tid);
    cp_commit();

    for (int s = 0; s < STAGES; s++) {
        if (s + 1 < STAGES) {
            gemm_produce(sb, s + 1, Ahb, Alb, Bb, tid);
            cp_commit();
            cp_wait1();
        } else {
            cp_wait0();
        }
        __syncthreads();
        gemm_stage_compute(sb + (s & 1) * GSTAGE, warp_m, warp_n, lr, lkb, acc);
        __syncthreads();
    }

    const int er = lane >> 2;
    const int ec = (lane & 3) * 2;
    if (z == 0) {
#pragma unroll
        for (int mi = 0; mi < 2; mi++)
#pragma unroll
            for (int ni = 0; ni < 8; ni++) {
                const int r = m0 + warp_m * 32 + mi * 16 + er;
                const int c = n0 + warp_n * 64 + ni * 8 + ec;
                uint32_t h, l;
                split2h(acc[mi][ni][0], acc[mi][ni][1], h, l);
                *(uint32_t*)(Qh + (size_t)r * N + c) = h;
                *(uint32_t*)(Ql + (size_t)r * N + c) = l;
                split2h(acc[mi][ni][2], acc[mi][ni][3], h, l);
                *(uint32_t*)(Qh + (size_t)(r + 8) * N + c) = h;
                *(uint32_t*)(Ql + (size_t)(r + 8) * N + c) = l;
            }
    } else {
        __half* C = (z == 1) ? Kv : Vv;
#pragma unroll
        for (int mi = 0; mi < 2; mi++)
#pragma unroll
            for (int ni = 0; ni < 8; ni++) {
                const int r = m0 + warp_m * 32 + mi * 16 + er;
                const int c = n0 + warp_n * 64 + ni * 8 + ec;
                *(uint32_t*)(C + (size_t)r * N + c) =
                    packh(acc[mi][ni][0], acc[mi][ni][1]);
                *(uint32_t*)(C + (size_t)(r + 8) * N + c) =
                    packh(acc[mi][ni][2], acc[mi][ni][3]);
            }
    }
}

// ===========================================================================
// gemm_out: out = X @ Wo^T (f32 out). Same geometry.
// ===========================================================================
__global__ __launch_bounds__(512, 1)
void gemm_out(const __half* __restrict__ Xh, const __half* __restrict__ Xl,
              const __half* __restrict__ wo, float* __restrict__ out)
{
    extern __shared__ char smc[];
    const uint32_t sb = smem_u32(smc);
    const int tid  = threadIdx.x;
    const int wid  = tid >> 5;
    const int lane = tid & 31;
    const int warp_m = wid & 7;
    const int warp_n = wid >> 3;
    const int m0 = blockIdx.y * 256;
    const int n0 = blockIdx.x * 128;
    const int N  = D_DIM;

    const __half* Ahb = Xh + (size_t)m0 * D_DIM;
    const __half* Alb = Xl + (size_t)m0 * D_DIM;
    const __half* Bb  = wo + (size_t)n0 * D_DIM;

    float acc[2][8][4];
#pragma unroll
    for (int mi = 0; mi < 2; mi++)
#pragma unroll
        for (int ni = 0; ni < 8; ni++)
#pragma unroll
            for (int q = 0; q < 4; q++) acc[mi][ni][q] = 0.f;

    const int lr  = lane & 15;
    const int lkb = (lane >> 4) << 4;

    gemm_produce(sb, 0, Ahb, Alb, Bb, tid);
    cp_commit();

    for (int s = 0; s < STAGES; s++) {
        if (s + 1 < STAGES) {
            gemm_produce(sb, s + 1, Ahb, Alb, Bb, tid);
            cp_commit();
            cp_wait1();
        } else {
            cp_wait0();
        }
        __syncthreads();
        gemm_stage_compute(sb + (s & 1) * GSTAGE, warp_m, warp_n, lr, lkb, acc);
        __syncthreads();
    }

    const int er = lane >> 2;
    const int ec = (lane & 3) * 2;
#pragma unroll
    for (int mi = 0; mi < 2; mi++)
#pragma unroll
        for (int ni = 0; ni < 8; ni++) {
            const int r = m0 + warp_m * 32 + mi * 16 + er;
            const int c = n0 + warp_n * 64 + ni * 8 + ec;
            *(float2*)(out + (size_t)r * N + c) =
                make_float2(acc[mi][ni][0], acc[mi][ni][1]);
            *(float2*)(out + (size_t)(r + 8) * N + c) =
                make_float2(acc[mi][ni][2], acc[mi][ni][3]);
        }
}

// ===========================================================================
// Flash attention (causal). CTA = 128 q-rows x (b,h), 256 threads, 8 warps.
// (byte-identical math to the 426.5us Round-7 version)
// ===========================================================================
constexpr int FQT  = 128 * SASB;           // 18432 per 128-row Q tile
constexpr int FQHI = 0;
constexpr int FQLO = FQHI + FQT;           // 18432
constexpr int FKV0 = FQLO + FQT;           // 36864
constexpr int KVT  = 64 * SASB;            // 9216 per 64-row tile
constexpr int KVBUF = 2 * KVT;             // 18432 (K, V)
constexpr int FSM_TOTAL = FKV0 + 2 * KVBUF;  // 73728

__global__ __launch_bounds__(256, 1)
void flash_mma(const __half* __restrict__ Qh, const __half* __restrict__ Ql,
               const __half* __restrict__ Kv, const __half* __restrict__ Vv,
               __half* __restrict__ Xh, __half* __restrict__ Xl)
{
    extern __shared__ char smc[];
    const uint32_t sb = smem_u32(smc);
    const int tid  = threadIdx.x;
    const int wid  = tid >> 5;
    const int lane = tid & 31;
    const int qb   = gridDim.x - 1 - blockIdx.x;   // longest blocks first
    const int h    = blockIdx.y;
    const int b    = blockIdx.z;

    const size_t head = (size_t)b * S_LEN * D_DIM + (size_t)h * DKH;
    const int prow = tid >> 3;
    const int pch  = tid & 7;

    {
        const __half* qb_[2] = {Qh + head, Ql + head};
#pragma unroll
        for (int i = 0; i < 8; i++) {
            const int t   = i >> 2;
            const int row = ((i & 3) << 5) | prow;
            const void* src = qb_[t] + (size_t)(qb * 128 + row) * D_DIM + pch * 8;
            cpasync16(sb + t * FQT + row * SASB + pch * 16, src);
        }
    }

    const __half* kvb[2] = {Kv + head, Vv + head};
    auto produce_kv = [&](int kb) {
        const uint32_t bufb = sb + FKV0 + (kb & 1) * KVBUF;
#pragma unroll
        for (int i = 0; i < 4; i++) {
            const int t   = i >> 1;
            const int row = ((i & 1) << 5) | prow;
            const void* src = kvb[t] + (size_t)(kb * 64 + row) * D_DIM + pch * 8;
            cpasync16(bufb + t * KVT + row * SASB + pch * 16, src);
        }
    };

    produce_kv(0);
    cp_commit();

    float o[8][4];
    float m0r = -1e30f, m1r = -1e30f, l0r = 0.f, l1r = 0.f;
#pragma unroll
    for (int ni = 0; ni < 8; ni++)
#pragma unroll
        for (int q = 0; q < 4; q++) o[ni][q] = 0.f;

    const int lr  = lane & 15;
    const int lkb = (lane >> 4) << 4;
    const int kb_max = 2 * qb + 1;

    for (int kb = 0; kb <= kb_max; kb++) {
        if (kb < kb_max) {
            produce_kv(kb + 1);
            cp_commit();
            cp_wait1();
        } else {
            cp_wait0();
        }
        __syncthreads();

        const uint32_t kvbase = sb + FKV0 + (kb & 1) * KVBUF;

        float sc[8][4];
#pragma unroll
        for (int ni = 0; ni < 8; ni++)
#pragma unroll
            for (int q = 0; q < 4; q++) sc[ni][q] = 0.f;

#pragma unroll
        for (int ks = 0; ks < 4; ks++) {
            const uint32_t abyte = (wid * 16 + lr) * SASB + ks * 32 + lkb;
            uint32_t qh[4], ql[4];
            ldmx4(qh, sb + FQHI + abyte);
            ldmx4(ql, sb + FQLO + abyte);
#pragma unroll
            for (int nb = 0; nb < 4; nb++) {
                const uint32_t bbyte = (nb * 16 + lr) * SASB + ks * 32 + lkb;
                uint32_t kh[4];
                ldmx4(kh, kvbase + bbyte);
                mma16816(sc[nb * 2],     qh, kh[0], kh[2]);
                mma16816(sc[nb * 2],     ql, kh[0], kh[2]);
                mma16816(sc[nb * 2 + 1], qh, kh[1], kh[3]);
                mma16816(sc[nb * 2 + 1], ql, kh[1], kh[3]);
            }
        }

#pragma unroll
        for (int ni = 0; ni < 8; ni++)
#pragma unroll
            for (int q = 0; q < 4; q++) sc[ni][q] *= 0.125f;

        const int q0 = qb * 128 + wid * 16 + (lane >> 2);
        if (kb * 64 + 63 > qb * 128 + wid * 16) {
#pragma unroll
            for (int ni = 0; ni < 8; ni++) {
#pragma unroll
                for (int c = 0; c < 2; c++) {
                    const int col = kb * 64 + ni * 8 + (lane & 3) * 2 + c;
                    if (col > q0)     sc[ni][c]     = -1e30f;
                    if (col > q0 + 8) sc[ni][2 + c] = -1e30f;
                }
            }
        }

        float mx0 = -1e30f, mx1 = -1e30f;
#pragma unroll
        for (int ni = 0; ni < 8; ni++) {
            mx0 = fmaxf(mx0, fmaxf(sc[ni][0], sc[ni][1]));
            mx1 = fmaxf(mx1, fmaxf(sc[ni][2], sc[ni][3]));
        }
        mx0 = fmaxf(mx0, __shfl_xor_sync(0xffffffffu, mx0, 1));
        mx0 = fmaxf(mx0, __shfl_xor_sync(0xffffffffu, mx0, 2));
        mx1 = fmaxf(mx1, __shfl_xor_sync(0xffffffffu, mx1, 1));
        mx1 = fmaxf(mx1, __shfl_xor_sync(0xffffffffu, mx1, 2));

        const float mn0 = fmaxf(m0r, mx0);
        const float mn1 = fmaxf(m1r, mx1);
        const float al0 = __expf(m0r - mn0);
        const float al1 = __expf(m1r - mn1);
        m0r = mn0; m1r = mn1;

        float ls0 = 0.f, ls1 = 0.f;
#pragma unroll
        for (int ni = 0; ni < 8; ni++) {
            sc[ni][0] = __expf(sc[ni][0] - mn0); ls0 += sc[ni][0];
            sc[ni][1] = __expf(sc[ni][1] - mn0); ls0 += sc[ni][1];
            sc[ni][2] = __expf(sc[ni][2] - mn1); ls1 += sc[ni][2];
            sc[ni][3] = __expf(sc[ni][3] - mn1); ls1 += sc[ni][3];
        }
        ls0 += __shfl_xor_sync(0xffffffffu, ls0, 1);
        ls0 += __shfl_xor_sync(0xffffffffu, ls0, 2);
        ls1 += __shfl_xor_sync(0xffffffffu, ls1, 1);
        ls1 += __shfl_xor_sync(0xffffffffu, ls1, 2);
        l0r = l0r * al0 + ls0;
        l1r = l1r * al1 + ls1;
#pragma unroll
        for (int ni = 0; ni < 8; ni++) {
            o[ni][0] *= al0; o[ni][1] *= al0;
            o[ni][2] *= al1; o[ni][3] *= al1;
        }

#pragma unroll
        for (int ks = 0; ks < 4; ks++) {
            uint32_t ph[4], pl[4];
            split2h(sc[2 * ks][0],     sc[2 * ks][1],     ph[0], pl[0]);
            split2h(sc[2 * ks][2],     sc[2 * ks][3],     ph[1], pl[1]);
            split2h(sc[2 * ks + 1][0], sc[2 * ks + 1][1], ph[2], pl[2]);
            split2h(sc[2 * ks + 1][2], sc[2 * ks + 1][3], ph[3], pl[3]);
#pragma unroll
            for (int nt = 0; nt < 4; nt++) {
                const uint32_t vbyte =
                    (ks * 16 + ((lane >> 3) & 1) * 8 + (lane & 7)) * SASB +
                    nt * 32 + ((lane >> 4) << 4);
                uint32_t vh[4];
                ldmx4t(vh, kvbase + KVT + vbyte);
                mma16816(o[nt * 2],     ph, vh[0], vh[1]);
                mma16816(o[nt * 2],     pl, vh[0], vh[1]);
                mma16816(o[nt * 2 + 1], ph, vh[2], vh[3]);
                mma16816(o[nt * 2 + 1], pl, vh[2], vh[3]);
            }
        }
        __syncthreads();
    }

    const float inv0 = 1.f / l0r;
    const float inv1 = 1.f / l1r;
    const int r0 = qb * 128 + wid * 16 + (lane >> 2);
    const int ec = (lane & 3) * 2;
#pragma unroll
    for (int ni = 0; ni < 8; ni++) {
        const size_t c = head + (size_t)ni * 8 + ec;
        uint32_t hh, ll;
        split2h(o[ni][0] * inv0, o[ni][1] * inv0, hh, ll);
        *(uint32_t*)(Xh + c + (size_t)r0 * D_DIM) = hh;
        *(uint32_t*)(Xl + c + (size_t)r0 * D_DIM) = ll;
        split2h(o[ni][2] * inv1, o[ni][3] * inv1, hh, ll);
        *(uint32_t*)(Xh + c + (size_t)(r0 + 8) * D_DIM) = hh;
        *(uint32_t*)(Xl + c + (size_t)(r0 + 8) * D_DIM) = ll;
    }
}

// ---------------------------------------------------------------------------
// launch
// ---------------------------------------------------------------------------
extern "C" void kernel_launch(void* const* d_in, const int* in_sizes, int n_in,
                              void* d_out, int out_size)
{
    const float* query = (const float*)d_in[0];
    const float* key   = (const float*)d_in[1];
    const float* value = (const float*)d_in[2];
    const float* Wq    = (const float*)d_in[3];
    const float* Wk    = (const float*)d_in[4];
    const float* Wv    = (const float*)d_in[5];
    const float* Wo    = (const float*)d_in[6];
    float* out = (float*)d_out;

    __half *aQh, *aQl, *aKh, *aKl, *aVh, *aVl, *wq, *wk, *wv, *wo;
    __half *Qh, *Ql, *Kv, *Vv, *Xh, *Xl;
    cudaGetSymbolAddress((void**)&aQh, g_aQh); cudaGetSymbolAddress((void**)&aQl, g_aQl);
    cudaGetSymbolAddress((void**)&aKh, g_aKh); cudaGetSymbolAddress((void**)&aKl, g_aKl);
    cudaGetSymbolAddress((void**)&aVh, g_aVh); cudaGetSymbolAddress((void**)&aVl, g_aVl);
    cudaGetSymbolAddress((void**)&wq, g_wq);   cudaGetSymbolAddress((void**)&wk, g_wk);
    cudaGetSymbolAddress((void**)&wv, g_wv);   cudaGetSymbolAddress((void**)&wo, g_wo);
    cudaGetSymbolAddress((void**)&Qh, g_Qh);   cudaGetSymbolAddress((void**)&Ql, g_Ql);
    cudaGetSymbolAddress((void**)&Kv, g_Kv);   cudaGetSymbolAddress((void**)&Vv, g_Vv);
    cudaGetSymbolAddress((void**)&Xh, g_Xh);   cudaGetSymbolAddress((void**)&Xl, g_Xl);

    cudaFuncSetAttribute(gemm_proj, cudaFuncAttributeMaxDynamicSharedMemorySize,
                         SM_GEMM_TOTAL);
    cudaFuncSetAttribute(gemm_out, cudaFuncAttributeMaxDynamicSharedMemorySize,
                         SM_GEMM_TOTAL);
    cudaFuncSetAttribute(flash_mma, cudaFuncAttributeMaxDynamicSharedMemorySize,
                         FSM_TOTAL);

    dim3 cgrid(256, 1, 7);
    convert_all<<<cgrid, 256>>>((const float4*)query, (const float4*)key,
                                (const float4*)value, (const float4*)Wq,
                                (const float4*)Wk, (const float4*)Wv,
                                (const float4*)Wo,
                                (uint2*)aQh, (uint2*)aQl, (uint2*)aKh, (uint2*)aKl,
                                (uint2*)aVh, (uint2*)aVl,
                                (uint2*)wq, (uint2*)wk, (uint2*)wv, (uint2*)wo);

    dim3 pgrid(D_DIM / 128, MTOT / 256, 3);   // (8, 16, 3)
    gemm_proj<<<pgrid, 512, SM_GEMM_TOTAL>>>(aQh, aQl, aKh, aKl, aVh, aVl,
                                             wq, wk, wv, Qh, Ql, Kv, Vv);

    dim3 fgrid(S_LEN / 128, H_NUM, B_SZ);     // (16, 16, 2)
    flash_mma<<<fgrid, 256, FSM_TOTAL>>>(Qh, Ql, Kv, Vv, Xh, Xl);

    dim3 ogrid(D_DIM / 128, MTOT / 256);      // (8, 16)
    gemm_out<<<ogrid, 512, SM_GEMM_TOTAL>>>(Xh, Xl, wo, out);
}

// round 12
// speedup vs baseline: 1.5585x; 1.5585x over previous
#include <cuda_runtime.h>
#include <cuda_fp16.h>
#include <math.h>
#include <stdint.h>

#define B_SZ  2
#define S_LEN 2048
#define D_DIM 1024
#define H_NUM 16
#define DKH   64
#define MTOT  (B_SZ * S_LEN)          // 4096

// ---------------------------------------------------------------------------
// Scratch (allocation-free rule: __device__ globals). fp16 operands.
// ---------------------------------------------------------------------------
__device__ __half g_aQh[MTOT * D_DIM], g_aQl[MTOT * D_DIM];  // split(query)
__device__ __half g_aKh[MTOT * D_DIM], g_aKl[MTOT * D_DIM];  // split(key)
__device__ __half g_aVh[MTOT * D_DIM], g_aVl[MTOT * D_DIM];  // split(value)
__device__ __half g_wq[D_DIM * D_DIM], g_wk[D_DIM * D_DIM];  // weights fp16
__device__ __half g_wv[D_DIM * D_DIM], g_wo[D_DIM * D_DIM];
__device__ __half g_Qh[MTOT * D_DIM], g_Ql[MTOT * D_DIM];    // Q proj (split)
__device__ __half g_Kv[MTOT * D_DIM];                        // K proj (single)
__device__ __half g_Vv[MTOT * D_DIM];                        // V proj (single)
__device__ __half g_Xh[MTOT * D_DIM], g_Xl[MTOT * D_DIM];    // attn out (split)

// ===========================================================================
// helpers
// ===========================================================================
__device__ __forceinline__ uint32_t smem_u32(const void* p) {
    uint32_t a;
    asm("{ .reg .u64 t; cvta.to.shared.u64 t, %1; cvt.u32.u64 %0, t; }"
        : "=r"(a) : "l"(p));
    return a;
}
__device__ __forceinline__ void ldmx4(uint32_t* r, uint32_t addr) {
    asm volatile("ldmatrix.sync.aligned.m8n8.x4.shared.b16 {%0,%1,%2,%3}, [%4];"
                 : "=r"(r[0]), "=r"(r[1]), "=r"(r[2]), "=r"(r[3]) : "r"(addr));
}
__device__ __forceinline__ void ldmx4t(uint32_t* r, uint32_t addr) {
    asm volatile("ldmatrix.sync.aligned.m8n8.x4.trans.shared.b16 {%0,%1,%2,%3}, [%4];"
                 : "=r"(r[0]), "=r"(r[1]), "=r"(r[2]), "=r"(r[3]) : "r"(addr));
}
__device__ __forceinline__ void mma16816(float* c, const uint32_t* a,
                                         uint32_t b0, uint32_t b1) {
    asm volatile(
        "mma.sync.aligned.m16n8k16.row.col.f32.f16.f16.f32 "
        "{%0,%1,%2,%3}, {%4,%5,%6,%7}, {%8,%9}, {%0,%1,%2,%3};"
        : "+f"(c[0]), "+f"(c[1]), "+f"(c[2]), "+f"(c[3])
        : "r"(a[0]), "r"(a[1]), "r"(a[2]), "r"(a[3]), "r"(b0), "r"(b1));
}
__device__ __forceinline__ uint32_t packh(float x, float y) {
    __half2 h = __float22half2_rn(make_float2(x, y));
    return *(uint32_t*)&h;
}
__device__ __forceinline__ void split2h(float x, float y, uint32_t& h, uint32_t& l) {
    h = packh(x, y);
    __half2 t = *(__half2*)&h;
    float2 f = __half22float2(t);
    l = packh(x - f.x, y - f.y);
}
__device__ __forceinline__ void cpasync16(uint32_t dst, const void* src) {
    asm volatile("cp.async.cg.shared.global [%0], [%1], 16;"
                 :: "r"(dst), "l"(src));
}
__device__ __forceinline__ void cp_commit() {
    asm volatile("cp.async.commit_group;" ::: "memory");
}
__device__ __forceinline__ void cp_wait0() {
    asm volatile("cp.async.wait_group 0;" ::: "memory");
}
__device__ __forceinline__ void cp_wait1() {
    asm volatile("cp.async.wait_group 1;" ::: "memory");
}

// ===========================================================================
// convert_all: z=0..2 split activations, z=3..6 convert weights (grid-stride)
// ===========================================================================
__global__ void convert_all(const float4* __restrict__ q, const float4* __restrict__ k,
                            const float4* __restrict__ v,
                            const float4* __restrict__ wq, const float4* __restrict__ wk,
                            const float4* __restrict__ wv, const float4* __restrict__ wo,
                            uint2* __restrict__ aqh, uint2* __restrict__ aql,
                            uint2* __restrict__ akh, uint2* __restrict__ akl,
                            uint2* __restrict__ avh, uint2* __restrict__ avl,
                            uint2* __restrict__ owq, uint2* __restrict__ owk,
                            uint2* __restrict__ owv, uint2* __restrict__ owo)
{
    const int z = blockIdx.z;
    const int stride = gridDim.x * blockDim.x;
    if (z < 3) {
        const float4* src = (z == 0) ? q : (z == 1) ? k : v;
        uint2* hi = (z == 0) ? aqh : (z == 1) ? akh : avh;
        uint2* lo = (z == 0) ? aql : (z == 1) ? akl : avl;
        const int n4 = MTOT * D_DIM / 4;
        for (int i = blockIdx.x * blockDim.x + threadIdx.x; i < n4; i += stride) {
            const float4 w = src[i];
            uint2 uh, ul;
            split2h(w.x, w.y, uh.x, ul.x);
            split2h(w.z, w.w, uh.y, ul.y);
            hi[i] = uh;
            lo[i] = ul;
        }
    } else {
        const float4* src = (z == 3) ? wq : (z == 4) ? wk : (z == 5) ? wv : wo;
        uint2* dst = (z == 3) ? owq : (z == 4) ? owk : (z == 5) ? owv : owo;
        const int n4 = D_DIM * D_DIM / 4;
        for (int i = blockIdx.x * blockDim.x + threadIdx.x; i < n4; i += stride) {
            const float4 w = src[i];
            dst[i] = make_uint2(packh(w.x, w.y), packh(w.z, w.w));
        }
    }
}

// ===========================================================================
// GEMM geometry: CTA tile 128x128, 256 threads = 8 warps (2m x 4n),
// warp tile 64x32 (acc 4x4 m16n8). K staged 64 fp16, cp.async double-buffer.
// 2 CTAs / SM (launch_bounds) so barrier/scoreboard stalls interleave.
// ===========================================================================
constexpr int SASB   = 144;                // padded row bytes (64 fp16 + pad)
constexpr int GT     = 128 * SASB;         // 18432 per 128-row tile
constexpr int GSTAGE = 3 * GT;             // 55296 per stage (Ahi, Alo, B)
constexpr int SM_GEMM_TOTAL = 2 * GSTAGE;  // 110592 (x2 CTAs = 216KB/SM)
constexpr int STAGES = D_DIM / 64;         // 16

__device__ __forceinline__ void gemm_stage_compute(
    uint32_t bufb, int warp_m, int warp_n, int lr, int lkb, float acc[4][4][4])
{
#pragma unroll
    for (int ks = 0; ks < 4; ks++) {
        const uint32_t kb = ks * 32 + lkb;
        uint32_t ah[4][4], al[4][4];
#pragma unroll
        for (int mi = 0; mi < 4; mi++) {
            const uint32_t byte = (warp_m * 64 + mi * 16 + lr) * SASB + kb;
            ldmx4(ah[mi], bufb + byte);
            ldmx4(al[mi], bufb + GT + byte);
        }
        uint32_t bh[4][2];
#pragma unroll
        for (int nb = 0; nb < 2; nb++) {
            const uint32_t byte = (warp_n * 32 + nb * 16 + lr) * SASB + kb;
            uint32_t r[4];
            ldmx4(r, bufb + 2 * GT + byte);
            bh[nb * 2][0] = r[0]; bh[nb * 2 + 1][0] = r[1];
            bh[nb * 2][1] = r[2]; bh[nb * 2 + 1][1] = r[3];
        }
#pragma unroll
        for (int mi = 0; mi < 4; mi++)
#pragma unroll
            for (int ni = 0; ni < 4; ni++) {
                mma16816(acc[mi][ni], ah[mi], bh[ni][0], bh[ni][1]);
                mma16816(acc[mi][ni], al[mi], bh[ni][0], bh[ni][1]);
            }
    }
}

// producer: 12 cp.async per thread per stage (3 tiles x 1024 16B-chunks)
__device__ __forceinline__ void gemm_produce(
    uint32_t sb, int s, const __half* Ahb, const __half* Alb, const __half* Bb,
    int tid)
{
    const uint32_t bufb = sb + (s & 1) * GSTAGE;
#pragma unroll
    for (int i = 0; i < 12; i++) {
        const int c = i * 256 + tid;          // 0..3071
        const int t = c >> 10;                // tile 0..2
        const int w = c & 1023;
        const int row = w >> 3, ch = w & 7;
        const __half* src = (t == 0) ? Ahb : (t == 1) ? Alb : Bb;
        cpasync16(bufb + t * GT + row * SASB + ch * 16,
                  src + (size_t)row * D_DIM + s * 64 + ch * 8);
    }
}

// ===========================================================================
// gemm_proj: z=0: Q (split out), z=1: K (single), z=2: V (single).
// ===========================================================================
__global__ __launch_bounds__(256, 2)
void gemm_proj(const __half* __restrict__ aQh, const __half* __restrict__ aQl,
               const __half* __restrict__ aKh, const __half* __restrict__ aKl,
               const __half* __restrict__ aVh, const __half* __restrict__ aVl,
               const __half* __restrict__ wq, const __half* __restrict__ wk,
               const __half* __restrict__ wv,
               __half* __restrict__ Qh, __half* __restrict__ Ql,
               __half* __restrict__ Kv, __half* __restrict__ Vv)
{
    extern __shared__ char smc[];
    const uint32_t sb = smem_u32(smc);
    const int tid  = threadIdx.x;
    const int wid  = tid >> 5;
    const int lane = tid & 31;
    const int warp_m = wid & 1;
    const int warp_n = wid >> 1;
    const int m0 = blockIdx.y * 128;
    const int n0 = blockIdx.x * 128;
    const int z  = blockIdx.z;
    const int N  = D_DIM;

    const __half* Ahb = ((z == 0) ? aQh : (z == 1) ? aKh : aVh) + (size_t)m0 * D_DIM;
    const __half* Alb = ((z == 0) ? aQl : (z == 1) ? aKl : aVl) + (size_t)m0 * D_DIM;
    const __half* Bb  = ((z == 0) ? wq  : (z == 1) ? wk  : wv)  + (size_t)n0 * D_DIM;

    float acc[4][4][4];
#pragma unroll
    for (int mi = 0; mi < 4; mi++)
#pragma unroll
        for (int ni = 0; ni < 4; ni++)
#pragma unroll
            for (int q = 0; q < 4; q++) acc[mi][ni][q] = 0.f;

    const int lr  = lane & 15;
    const int lkb = (lane >> 4) << 4;

    gemm_produce(sb, 0, Ahb, Alb, Bb, tid);
    cp_commit();

    for (int s = 0; s < STAGES; s++) {
        if (s + 1 < STAGES) {
            gemm_produce(sb, s + 1, Ahb, Alb, Bb, tid);
            cp_commit();
            cp_wait1();
        } else {
            cp_wait0();
        }
        __syncthreads();
        gemm_stage_compute(sb + (s & 1) * GSTAGE, warp_m, warp_n, lr, lkb, acc);
        __syncthreads();
    }

    const int er = lane >> 2;
    const int ec = (lane & 3) * 2;
    if (z == 0) {
#pragma unroll
        for (int mi = 0; mi < 4; mi++)
#pragma unroll
            for (int ni = 0; ni < 4; ni++) {
                const int r = m0 + warp_m * 64 + mi * 16 + er;
                const int c = n0 + warp_n * 32 + ni * 8 + ec;
                uint32_t h, l;
                split2h(acc[mi][ni][0], acc[mi][ni][1], h, l);
                *(uint32_t*)(Qh + (size_t)r * N + c) = h;
                *(uint32_t*)(Ql + (size_t)r * N + c) = l;
                split2h(acc[mi][ni][2], acc[mi][ni][3], h, l);
                *(uint32_t*)(Qh + (size_t)(r + 8) * N + c) = h;
                *(uint32_t*)(Ql + (size_t)(r + 8) * N + c) = l;
            }
    } else {
        __half* C = (z == 1) ? Kv : Vv;
#pragma unroll
        for (int mi = 0; mi < 4; mi++)
#pragma unroll
            for (int ni = 0; ni < 4; ni++) {
                const int r = m0 + warp_m * 64 + mi * 16 + er;
                const int c = n0 + warp_n * 32 + ni * 8 + ec;
                *(uint32_t*)(C + (size_t)r * N + c) =
                    packh(acc[mi][ni][0], acc[mi][ni][1]);
                *(uint32_t*)(C + (size_t)(r + 8) * N + c) =
                    packh(acc[mi][ni][2], acc[mi][ni][3]);
            }
    }
}

// ===========================================================================
// gemm_out: out = X @ Wo^T (f32 out). Same geometry.
// ===========================================================================
__global__ __launch_bounds__(256, 2)
void gemm_out(const __half* __restrict__ Xh, const __half* __restrict__ Xl,
              const __half* __restrict__ wo, float* __restrict__ out)
{
    extern __shared__ char smc[];
    const uint32_t sb = smem_u32(smc);
    const int tid  = threadIdx.x;
    const int wid  = tid >> 5;
    const int lane = tid & 31;
    const int warp_m = wid & 1;
    const int warp_n = wid >> 1;
    const int m0 = blockIdx.y * 128;
    const int n0 = blockIdx.x * 128;
    const int N  = D_DIM;

    const __half* Ahb = Xh + (size_t)m0 * D_DIM;
    const __half* Alb = Xl + (size_t)m0 * D_DIM;
    const __half* Bb  = wo + (size_t)n0 * D_DIM;

    float acc[4][4][4];
#pragma unroll
    for (int mi = 0; mi < 4; mi++)
#pragma unroll
        for (int ni = 0; ni < 4; ni++)
#pragma unroll
            for (int q = 0; q < 4; q++) acc[mi][ni][q] = 0.f;

    const int lr  = lane & 15;
    const int lkb = (lane >> 4) << 4;

    gemm_produce(sb, 0, Ahb, Alb, Bb, tid);
    cp_commit();

    for (int s = 0; s < STAGES; s++) {
        if (s + 1 < STAGES) {
            gemm_produce(sb, s + 1, Ahb, Alb, Bb, tid);
            cp_commit();
            cp_wait1();
        } else {
            cp_wait0();
        }
        __syncthreads();
        gemm_stage_compute(sb + (s & 1) * GSTAGE, warp_m, warp_n, lr, lkb, acc);
        __syncthreads();
    }

    const int er = lane >> 2;
    const int ec = (lane & 3) * 2;
#pragma unroll
    for (int mi = 0; mi < 4; mi++)
#pragma unroll
        for (int ni = 0; ni < 4; ni++) {
            const int r = m0 + warp_m * 64 + mi * 16 + er;
            const int c = n0 + warp_n * 32 + ni * 8 + ec;
            *(float2*)(out + (size_t)r * N + c) =
                make_float2(acc[mi][ni][0], acc[mi][ni][1]);
            *(float2*)(out + (size_t)(r + 8) * N + c) =
                make_float2(acc[mi][ni][2], acc[mi][ni][3]);
        }
}

// ===========================================================================
// Flash attention (causal). CTA = 128 q-rows x (b,h), 256 threads, 8 warps.
// Same math as the 426.5us version; now 2 CTAs/SM via launch_bounds.
// ===========================================================================
constexpr int FQT  = 128 * SASB;           // 18432 per 128-row Q tile
constexpr int FQHI = 0;
constexpr int FQLO = FQHI + FQT;           // 18432
constexpr int FKV0 = FQLO + FQT;           // 36864
constexpr int KVT  = 64 * SASB;            // 9216 per 64-row tile
constexpr int KVBUF = 2 * KVT;             // 18432 (K, V)
constexpr int FSM_TOTAL = FKV0 + 2 * KVBUF;  // 73728 (x2 CTAs = 144KB/SM)

__global__ __launch_bounds__(256, 2)
void flash_mma(const __half* __restrict__ Qh, const __half* __restrict__ Ql,
               const __half* __restrict__ Kv, const __half* __restrict__ Vv,
               __half* __restrict__ Xh, __half* __restrict__ Xl)
{
    extern __shared__ char smc[];
    const uint32_t sb = smem_u32(smc);
    const int tid  = threadIdx.x;
    const int wid  = tid >> 5;
    const int lane = tid & 31;
    const int qb   = gridDim.x - 1 - blockIdx.x;   // longest blocks first
    const int h    = blockIdx.y;
    const int b    = blockIdx.z;

    const size_t head = (size_t)b * S_LEN * D_DIM + (size_t)h * DKH;
    const int prow = tid >> 3;
    const int pch  = tid & 7;

    {
        const __half* qb_[2] = {Qh + head, Ql + head};
#pragma unroll
        for (int i = 0; i < 8; i++) {
            const int t   = i >> 2;
            const int row = ((i & 3) << 5) | prow;
            const void* src = qb_[t] + (size_t)(qb * 128 + row) * D_DIM + pch * 8;
            cpasync16(sb + t * FQT + row * SASB + pch * 16, src);
        }
    }

    const __half* kvb[2] = {Kv + head, Vv + head};
    auto produce_kv = [&](int kb) {
        const uint32_t bufb = sb + FKV0 + (kb & 1) * KVBUF;
#pragma unroll
        for (int i = 0; i < 4; i++) {
            const int t   = i >> 1;
            const int row = ((i & 1) << 5) | prow;
            const void* src = kvb[t] + (size_t)(kb * 64 + row) * D_DIM + pch * 8;
            cpasync16(bufb + t * KVT + row * SASB + pch * 16, src);
        }
    };

    produce_kv(0);
    cp_commit();

    float o[8][4];
    float m0r = -1e30f, m1r = -1e30f, l0r = 0.f, l1r = 0.f;
#pragma unroll
    for (int ni = 0; ni < 8; ni++)
#pragma unroll
        for (int q = 0; q < 4; q++) o[ni][q] = 0.f;

    const int lr  = lane & 15;
    const int lkb = (lane >> 4) << 4;
    const int kb_max = 2 * qb + 1;

    for (int kb = 0; kb <= kb_max; kb++) {
        if (kb < kb_max) {
            produce_kv(kb + 1);
            cp_commit();
            cp_wait1();
        } else {
            cp_wait0();
        }
        __syncthreads();

        const uint32_t kvbase = sb + FKV0 + (kb & 1) * KVBUF;

        float sc[8][4];
#pragma unroll
        for (int ni = 0; ni < 8; ni++)
#pragma unroll
            for (int q = 0; q < 4; q++) sc[ni][q] = 0.f;

#pragma unroll
        for (int ks = 0; ks < 4; ks++) {
            const uint32_t abyte = (wid * 16 + lr) * SASB + ks * 32 + lkb;
            uint32_t qh[4], ql[4];
            ldmx4(qh, sb + FQHI + abyte);
            ldmx4(ql, sb + FQLO + abyte);
#pragma unroll
            for (int nb = 0; nb < 4; nb++) {
                const uint32_t bbyte = (nb * 16 + lr) * SASB + ks * 32 + lkb;
                uint32_t kh[4];
                ldmx4(kh, kvbase + bbyte);
                mma16816(sc[nb * 2],     qh, kh[0], kh[2]);
                mma16816(sc[nb * 2],     ql, kh[0], kh[2]);
                mma16816(sc[nb * 2 + 1], qh, kh[1], kh[3]);
                mma16816(sc[nb * 2 + 1], ql, kh[1], kh[3]);
            }
        }

#pragma unroll
        for (int ni = 0; ni < 8; ni++)
#pragma unroll
            for (int q = 0; q < 4; q++) sc[ni][q] *= 0.125f;

        const int q0 = qb * 128 + wid * 16 + (lane >> 2);
        if (kb * 64 + 63 > qb * 128 + wid * 16) {
#pragma unroll
            for (int ni = 0; ni < 8; ni++) {
#pragma unroll
                for (int c = 0; c < 2; c++) {
                    const int col = kb * 64 + ni * 8 + (lane & 3) * 2 + c;
                    if (col > q0)     sc[ni][c]     = -1e30f;
                    if (col > q0 + 8) sc[ni][2 + c] = -1e30f;
                }
            }
        }

        float mx0 = -1e30f, mx1 = -1e30f;
#pragma unroll
        for (int ni = 0; ni < 8; ni++) {
            mx0 = fmaxf(mx0, fmaxf(sc[ni][0], sc[ni][1]));
            mx1 = fmaxf(mx1, fmaxf(sc[ni][2], sc[ni][3]));
        }
        mx0 = fmaxf(mx0, __shfl_xor_sync(0xffffffffu, mx0, 1));
        mx0 = fmaxf(mx0, __shfl_xor_sync(0xffffffffu, mx0, 2));
        mx1 = fmaxf(mx1, __shfl_xor_sync(0xffffffffu, mx1, 1));
        mx1 = fmaxf(mx1, __shfl_xor_sync(0xffffffffu, mx1, 2));

        const float mn0 = fmaxf(m0r, mx0);
        const float mn1 = fmaxf(m1r, mx1);
        const float al0 = __expf(m0r - mn0);
        const float al1 = __expf(m1r - mn1);
        m0r = mn0; m1r = mn1;

        float ls0 = 0.f, ls1 = 0.f;
#pragma unroll
        for (int ni = 0; ni < 8; ni++) {
            sc[ni][0] = __expf(sc[ni][0] - mn0); ls0 += sc[ni][0];
            sc[ni][1] = __expf(sc[ni][1] - mn0); ls0 += sc[ni][1];
            sc[ni][2] = __expf(sc[ni][2] - mn1); ls1 += sc[ni][2];
            sc[ni][3] = __expf(sc[ni][3] - mn1); ls1 += sc[ni][3];
        }
        ls0 += __shfl_xor_sync(0xffffffffu, ls0, 1);
        ls0 += __shfl_xor_sync(0xffffffffu, ls0, 2);
        ls1 += __shfl_xor_sync(0xffffffffu, ls1, 1);
        ls1 += __shfl_xor_sync(0xffffffffu, ls1, 2);
        l0r = l0r * al0 + ls0;
        l1r = l1r * al1 + ls1;
#pragma unroll
        for (int ni = 0; ni < 8; ni++) {
            o[ni][0] *= al0; o[ni][1] *= al0;
            o[ni][2] *= al1; o[ni][3] *= al1;
        }

#pragma unroll
        for (int ks = 0; ks < 4; ks++) {
            uint32_t ph[4], pl[4];
            split2h(sc[2 * ks][0],     sc[2 * ks][1],     ph[0], pl[0]);
            split2h(sc[2 * ks][2],     sc[2 * ks][3],     ph[1], pl[1]);
            split2h(sc[2 * ks + 1][0], sc[2 * ks + 1][1], ph[2], pl[2]);
            split2h(sc[2 * ks + 1][2], sc[2 * ks + 1][3], ph[3], pl[3]);
#pragma unroll
            for (int nt = 0; nt < 4; nt++) {
                const uint32_t vbyte =
                    (ks * 16 + ((lane >> 3) & 1) * 8 + (lane & 7)) * SASB +
                    nt * 32 + ((lane >> 4) << 4);
                uint32_t vh[4];
                ldmx4t(vh, kvbase + KVT + vbyte);
                mma16816(o[nt * 2],     ph, vh[0], vh[1]);
                mma16816(o[nt * 2],     pl, vh[0], vh[1]);
                mma16816(o[nt * 2 + 1], ph, vh[2], vh[3]);
                mma16816(o[nt * 2 + 1], pl, vh[2], vh[3]);
            }
        }
        __syncthreads();
    }

    const float inv0 = 1.f / l0r;
    const float inv1 = 1.f / l1r;
    const int r0 = qb * 128 + wid * 16 + (lane >> 2);
    const int ec = (lane & 3) * 2;
#pragma unroll
    for (int ni = 0; ni < 8; ni++) {
        const size_t c = head + (size_t)ni * 8 + ec;
        uint32_t hh, ll;
        split2h(o[ni][0] * inv0, o[ni][1] * inv0, hh, ll);
        *(uint32_t*)(Xh + c + (size_t)r0 * D_DIM) = hh;
        *(uint32_t*)(Xl + c + (size_t)r0 * D_DIM) = ll;
        split2h(o[ni][2] * inv1, o[ni][3] * inv1, hh, ll);
        *(uint32_t*)(Xh + c + (size_t)(r0 + 8) * D_DIM) = hh;
        *(uint32_t*)(Xl + c + (size_t)(r0 + 8) * D_DIM) = ll;
    }
}

// ---------------------------------------------------------------------------
// launch
// ---------------------------------------------------------------------------
extern "C" void kernel_launch(void* const* d_in, const int* in_sizes, int n_in,
                              void* d_out, int out_size)
{
    const float* query = (const float*)d_in[0];
    const float* key   = (const float*)d_in[1];
    const float* value = (const float*)d_in[2];
    const float* Wq    = (const float*)d_in[3];
    const float* Wk    = (const float*)d_in[4];
    const float* Wv    = (const float*)d_in[5];
    const float* Wo    = (const float*)d_in[6];
    float* out = (float*)d_out;

    __half *aQh, *aQl, *aKh, *aKl, *aVh, *aVl, *wq, *wk, *wv, *wo;
    __half *Qh, *Ql, *Kv, *Vv, *Xh, *Xl;
    cudaGetSymbolAddress((void**)&aQh, g_aQh); cudaGetSymbolAddress((void**)&aQl, g_aQl);
    cudaGetSymbolAddress((void**)&aKh, g_aKh); cudaGetSymbolAddress((void**)&aKl, g_aKl);
    cudaGetSymbolAddress((void**)&aVh, g_aVh); cudaGetSymbolAddress((void**)&aVl, g_aVl);
    cudaGetSymbolAddress((void**)&wq, g_wq);   cudaGetSymbolAddress((void**)&wk, g_wk);
    cudaGetSymbolAddress((void**)&wv, g_wv);   cudaGetSymbolAddress((void**)&wo, g_wo);
    cudaGetSymbolAddress((void**)&Qh, g_Qh);   cudaGetSymbolAddress((void**)&Ql, g_Ql);
    cudaGetSymbolAddress((void**)&Kv, g_Kv);   cudaGetSymbolAddress((void**)&Vv, g_Vv);
    cudaGetSymbolAddress((void**)&Xh, g_Xh);   cudaGetSymbolAddress((void**)&Xl, g_Xl);

    cudaFuncSetAttribute(gemm_proj, cudaFuncAttributeMaxDynamicSharedMemorySize,
                         SM_GEMM_TOTAL);
    cudaFuncSetAttribute(gemm_out, cudaFuncAttributeMaxDynamicSharedMemorySize,
                         SM_GEMM_TOTAL);
    cudaFuncSetAttribute(flash_mma, cudaFuncAttributeMaxDynamicSharedMemorySize,
                         FSM_TOTAL);

    dim3 cgrid(256, 1, 7);
    convert_all<<<cgrid, 256>>>((const float4*)query, (const float4*)key,
                                (const float4*)value, (const float4*)Wq,
                                (const float4*)Wk, (const float4*)Wv,
                                (const float4*)Wo,
                                (uint2*)aQh, (uint2*)aQl, (uint2*)aKh, (uint2*)aKl,
                                (uint2*)aVh, (uint2*)aVl,
                                (uint2*)wq, (uint2*)wk, (uint2*)wv, (uint2*)wo);

    dim3 pgrid(D_DIM / 128, MTOT / 128, 3);   // (8, 32, 3)
    gemm_proj<<<pgrid, 256, SM_GEMM_TOTAL>>>(aQh, aQl, aKh, aKl, aVh, aVl,
                                             wq, wk, wv, Qh, Ql, Kv, Vv);

    dim3 fgrid(S_LEN / 128, H_NUM, B_SZ);     // (16, 16, 2)
    flash_mma<<<fgrid, 256, FSM_TOTAL>>>(Qh, Ql, Kv, Vv, Xh, Xl);

    dim3 ogrid(D_DIM / 128, MTOT / 128);      // (8, 32)
    gemm_out<<<ogrid, 256, SM_GEMM_TOTAL>>>(Xh, Xl, wo, out);
}

// round 13
// speedup vs baseline: 1.5594x; 1.0006x over previous
#include <cuda_runtime.h>
#include <cuda_fp16.h>
#include <math.h>
#include <stdint.h>

#define B_SZ  2
#define S_LEN 2048
#define D_DIM 1024
#define H_NUM 16
#define DKH   64
#define MTOT  (B_SZ * S_LEN)          // 4096

// ---------------------------------------------------------------------------
// Scratch (allocation-free rule: __device__ globals). fp16 operands.
// ---------------------------------------------------------------------------
__device__ __half g_aQh[MTOT * D_DIM], g_aQl[MTOT * D_DIM];  // split(query)
__device__ __half g_aKh[MTOT * D_DIM], g_aKl[MTOT * D_DIM];  // split(key)
__device__ __half g_aVh[MTOT * D_DIM], g_aVl[MTOT * D_DIM];  // split(value)
__device__ __half g_wq[D_DIM * D_DIM], g_wk[D_DIM * D_DIM];  // weights fp16
__device__ __half g_wv[D_DIM * D_DIM], g_wo[D_DIM * D_DIM];
__device__ __half g_Qh[MTOT * D_DIM], g_Ql[MTOT * D_DIM];    // Q proj (split)
__device__ __half g_Kv[MTOT * D_DIM];                        // K proj (single)
__device__ __half g_Vv[MTOT * D_DIM];                        // V proj (single)
__device__ __half g_Xh[MTOT * D_DIM], g_Xl[MTOT * D_DIM];    // attn out (split)

// ===========================================================================
// helpers
// ===========================================================================
__device__ __forceinline__ uint32_t smem_u32(const void* p) {
    uint32_t a;
    asm("{ .reg .u64 t; cvta.to.shared.u64 t, %1; cvt.u32.u64 %0, t; }"
        : "=r"(a) : "l"(p));
    return a;
}
__device__ __forceinline__ void ldmx4(uint32_t* r, uint32_t addr) {
    asm volatile("ldmatrix.sync.aligned.m8n8.x4.shared.b16 {%0,%1,%2,%3}, [%4];"
                 : "=r"(r[0]), "=r"(r[1]), "=r"(r[2]), "=r"(r[3]) : "r"(addr));
}
__device__ __forceinline__ void ldmx4t(uint32_t* r, uint32_t addr) {
    asm volatile("ldmatrix.sync.aligned.m8n8.x4.trans.shared.b16 {%0,%1,%2,%3}, [%4];"
                 : "=r"(r[0]), "=r"(r[1]), "=r"(r[2]), "=r"(r[3]) : "r"(addr));
}
// NOTE: non-volatile on purpose — pure register op; lets ptxas interleave
// independent accumulators instead of stalling on back-to-back RAW HMMAs.
__device__ __forceinline__ void mma16816(float* c, const uint32_t* a,
                                         uint32_t b0, uint32_t b1) {
    asm("mma.sync.aligned.m16n8k16.row.col.f32.f16.f16.f32 "
        "{%0,%1,%2,%3}, {%4,%5,%6,%7}, {%8,%9}, {%0,%1,%2,%3};"
        : "+f"(c[0]), "+f"(c[1]), "+f"(c[2]), "+f"(c[3])
        : "r"(a[0]), "r"(a[1]), "r"(a[2]), "r"(a[3]), "r"(b0), "r"(b1));
}
__device__ __forceinline__ uint32_t packh(float x, float y) {
    __half2 h = __float22half2_rn(make_float2(x, y));
    return *(uint32_t*)&h;
}
__device__ __forceinline__ void split2h(float x, float y, uint32_t& h, uint32_t& l) {
    h = packh(x, y);
    __half2 t = *(__half2*)&h;
    float2 f = __half22float2(t);
    l = packh(x - f.x, y - f.y);
}
__device__ __forceinline__ void cpasync16(uint32_t dst, const void* src) {
    asm volatile("cp.async.cg.shared.global [%0], [%1], 16;"
                 :: "r"(dst), "l"(src));
}
__device__ __forceinline__ void cp_commit() {
    asm volatile("cp.async.commit_group;" ::: "memory");
}
__device__ __forceinline__ void cp_wait0() {
    asm volatile("cp.async.wait_group 0;" ::: "memory");
}
__device__ __forceinline__ void cp_wait1() {
    asm volatile("cp.async.wait_group 1;" ::: "memory");
}

// ===========================================================================
// convert_all: z=0..2 split activations, z=3..6 convert weights (grid-stride)
// ===========================================================================
__global__ void convert_all(const float4* __restrict__ q, const float4* __restrict__ k,
                            const float4* __restrict__ v,
                            const float4* __restrict__ wq, const float4* __restrict__ wk,
                            const float4* __restrict__ wv, const float4* __restrict__ wo,
                            uint2* __restrict__ aqh, uint2* __restrict__ aql,
                            uint2* __restrict__ akh, uint2* __restrict__ akl,
                            uint2* __restrict__ avh, uint2* __restrict__ avl,
                            uint2* __restrict__ owq, uint2* __restrict__ owk,
                            uint2* __restrict__ owv, uint2* __restrict__ owo)
{
    const int z = blockIdx.z;
    const int stride = gridDim.x * blockDim.x;
    if (z < 3) {
        const float4* src = (z == 0) ? q : (z == 1) ? k : v;
        uint2* hi = (z == 0) ? aqh : (z == 1) ? akh : avh;
        uint2* lo = (z == 0) ? aql : (z == 1) ? akl : avl;
        const int n4 = MTOT * D_DIM / 4;
        for (int i = blockIdx.x * blockDim.x + threadIdx.x; i < n4; i += stride) {
            const float4 w = src[i];
            uint2 uh, ul;
            split2h(w.x, w.y, uh.x, ul.x);
            split2h(w.z, w.w, uh.y, ul.y);
            hi[i] = uh;
            lo[i] = ul;
        }
    } else {
        const float4* src = (z == 3) ? wq : (z == 4) ? wk : (z == 5) ? wv : wo;
        uint2* dst = (z == 3) ? owq : (z == 4) ? owk : (z == 5) ? owv : owo;
        const int n4 = D_DIM * D_DIM / 4;
        for (int i = blockIdx.x * blockDim.x + threadIdx.x; i < n4; i += stride) {
            const float4 w = src[i];
            dst[i] = make_uint2(packh(w.x, w.y), packh(w.z, w.w));
        }
    }
}

// ===========================================================================
// GEMM geometry: CTA tile 128x128, 256 threads = 8 warps (2m x 4n),
// warp tile 64x32 (acc 4x4 m16n8). K staged 64 fp16, cp.async double-buffer.
// 2 CTAs / SM.
// ===========================================================================
constexpr int SASB   = 144;                // padded row bytes (64 fp16 + pad)
constexpr int GT     = 128 * SASB;         // 18432 per 128-row tile
constexpr int GSTAGE = 3 * GT;             // 55296 per stage (Ahi, Alo, B)
constexpr int SM_GEMM_TOTAL = 2 * GSTAGE;  // 110592 (x2 CTAs = 216KB/SM)
constexpr int STAGES = D_DIM / 64;         // 16

__device__ __forceinline__ void gemm_stage_compute(
    uint32_t bufb, int warp_m, int warp_n, int lr, int lkb, float acc[4][4][4])
{
#pragma unroll
    for (int ks = 0; ks < 4; ks++) {
        const uint32_t kb = ks * 32 + lkb;
        uint32_t ah[4][4], al[4][4];
#pragma unroll
        for (int mi = 0; mi < 4; mi++) {
            const uint32_t byte = (warp_m * 64 + mi * 16 + lr) * SASB + kb;
            ldmx4(ah[mi], bufb + byte);
            ldmx4(al[mi], bufb + GT + byte);
        }
        uint32_t bh[4][2];
#pragma unroll
        for (int nb = 0; nb < 2; nb++) {
            const uint32_t byte = (warp_n * 32 + nb * 16 + lr) * SASB + kb;
            uint32_t r[4];
            ldmx4(r, bufb + 2 * GT + byte);
            bh[nb * 2][0] = r[0]; bh[nb * 2 + 1][0] = r[1];
            bh[nb * 2][1] = r[2]; bh[nb * 2 + 1][1] = r[3];
        }
        // all hi-term MMAs first (16 independent accs), then all lo-term MMAs:
        // dependent pairs are 16 instructions apart instead of adjacent.
#pragma unroll
        for (int mi = 0; mi < 4; mi++)
#pragma unroll
            for (int ni = 0; ni < 4; ni++)
                mma16816(acc[mi][ni], ah[mi], bh[ni][0], bh[ni][1]);
#pragma unroll
        for (int mi = 0; mi < 4; mi++)
#pragma unroll
            for (int ni = 0; ni < 4; ni++)
                mma16816(acc[mi][ni], al[mi], bh[ni][0], bh[ni][1]);
    }
}

// producer: 12 cp.async per thread per stage (3 tiles x 1024 16B-chunks)
__device__ __forceinline__ void gemm_produce(
    uint32_t sb, int s, const __half* Ahb, const __half* Alb, const __half* Bb,
    int tid)
{
    const uint32_t bufb = sb + (s & 1) * GSTAGE;
#pragma unroll
    for (int i = 0; i < 12; i++) {
        const int c = i * 256 + tid;          // 0..3071
        const int t = c >> 10;                // tile 0..2
        const int w = c & 1023;
        const int row = w >> 3, ch = w & 7;
        const __half* src = (t == 0) ? Ahb : (t == 1) ? Alb : Bb;
        cpasync16(bufb + t * GT + row * SASB + ch * 16,
                  src + (size_t)row * D_DIM + s * 64 + ch * 8);
    }
}

// ===========================================================================
// gemm_proj: z=0: Q (split out), z=1: K (single), z=2: V (single).
// ===========================================================================
__global__ __launch_bounds__(256, 2)
void gemm_proj(const __half* __restrict__ aQh, const __half* __restrict__ aQl,
               const __half* __restrict__ aKh, const __half* __restrict__ aKl,
               const __half* __restrict__ aVh, const __half* __restrict__ aVl,
               const __half* __restrict__ wq, const __half* __restrict__ wk,
               const __half* __restrict__ wv,
               __half* __restrict__ Qh, __half* __restrict__ Ql,
               __half* __restrict__ Kv, __half* __restrict__ Vv)
{
    extern __shared__ char smc[];
    const uint32_t sb = smem_u32(smc);
    const int tid  = threadIdx.x;
    const int wid  = tid >> 5;
    const int lane = tid & 31;
    const int warp_m = wid & 1;
    const int warp_n = wid >> 1;
    const int m0 = blockIdx.y * 128;
    const int n0 = blockIdx.x * 128;
    const int z  = blockIdx.z;
    const int N  = D_DIM;

    const __half* Ahb = ((z == 0) ? aQh : (z == 1) ? aKh : aVh) + (size_t)m0 * D_DIM;
    const __half* Alb = ((z == 0) ? aQl : (z == 1) ? aKl : aVl) + (size_t)m0 * D_DIM;
    const __half* Bb  = ((z == 0) ? wq  : (z == 1) ? wk  : wv)  + (size_t)n0 * D_DIM;

    float acc[4][4][4];
#pragma unroll
    for (int mi = 0; mi < 4; mi++)
#pragma unroll
        for (int ni = 0; ni < 4; ni++)
#pragma unroll
            for (int q = 0; q < 4; q++) acc[mi][ni][q] = 0.f;

    const int lr  = lane & 15;
    const int lkb = (lane >> 4) << 4;

    gemm_produce(sb, 0, Ahb, Alb, Bb, tid);
    cp_commit();

    for (int s = 0; s < STAGES; s++) {
        if (s + 1 < STAGES) {
            gemm_produce(sb, s + 1, Ahb, Alb, Bb, tid);
            cp_commit();
            cp_wait1();
        } else {
            cp_wait0();
        }
        __syncthreads();
        gemm_stage_compute(sb + (s & 1) * GSTAGE, warp_m, warp_n, lr, lkb, acc);
        __syncthreads();
    }

    const int er = lane >> 2;
    const int ec = (lane & 3) * 2;
    if (z == 0) {
#pragma unroll
        for (int mi = 0; mi < 4; mi++)
#pragma unroll
            for (int ni = 0; ni < 4; ni++) {
                const int r = m0 + warp_m * 64 + mi * 16 + er;
                const int c = n0 + warp_n * 32 + ni * 8 + ec;
                uint32_t h, l;
                split2h(acc[mi][ni][0], acc[mi][ni][1], h, l);
                *(uint32_t*)(Qh + (size_t)r * N + c) = h;
                *(uint32_t*)(Ql + (size_t)r * N + c) = l;
                split2h(acc[mi][ni][2], acc[mi][ni][3], h, l);
                *(uint32_t*)(Qh + (size_t)(r + 8) * N + c) = h;
                *(uint32_t*)(Ql + (size_t)(r + 8) * N + c) = l;
            }
    } else {
        __half* C = (z == 1) ? Kv : Vv;
#pragma unroll
        for (int mi = 0; mi < 4; mi++)
#pragma unroll
            for (int ni = 0; ni < 4; ni++) {
                const int r = m0 + warp_m * 64 + mi * 16 + er;
                const int c = n0 + warp_n * 32 + ni * 8 + ec;
                *(uint32_t*)(C + (size_t)r * N + c) =
                    packh(acc[mi][ni][0], acc[mi][ni][1]);
                *(uint32_t*)(C + (size_t)(r + 8) * N + c) =
                    packh(acc[mi][ni][2], acc[mi][ni][3]);
            }
    }
}

// ===========================================================================
// gemm_out: out = X @ Wo^T (f32 out). Same geometry.
// ===========================================================================
__global__ __launch_bounds__(256, 2)
void gemm_out(const __half* __restrict__ Xh, const __half* __restrict__ Xl,
              const __half* __restrict__ wo, float* __restrict__ out)
{
    extern __shared__ char smc[];
    const uint32_t sb = smem_u32(smc);
    const int tid  = threadIdx.x;
    const int wid  = tid >> 5;
    const int lane = tid & 31;
    const int warp_m = wid & 1;
    const int warp_n = wid >> 1;
    const int m0 = blockIdx.y * 128;
    const int n0 = blockIdx.x * 128;
    const int N  = D_DIM;

    const __half* Ahb = Xh + (size_t)m0 * D_DIM;
    const __half* Alb = Xl + (size_t)m0 * D_DIM;
    const __half* Bb  = wo + (size_t)n0 * D_DIM;

    float acc[4][4][4];
#pragma unroll
    for (int mi = 0; mi < 4; mi++)
#pragma unroll
        for (int ni = 0; ni < 4; ni++)
#pragma unroll
            for (int q = 0; q < 4; q++) acc[mi][ni][q] = 0.f;

    const int lr  = lane & 15;
    const int lkb = (lane >> 4) << 4;

    gemm_produce(sb, 0, Ahb, Alb, Bb, tid);
    cp_commit();

    for (int s = 0; s < STAGES; s++) {
        if (s + 1 < STAGES) {
            gemm_produce(sb, s + 1, Ahb, Alb, Bb, tid);
            cp_commit();
            cp_wait1();
        } else {
            cp_wait0();
        }
        __syncthreads();
        gemm_stage_compute(sb + (s & 1) * GSTAGE, warp_m, warp_n, lr, lkb, acc);
        __syncthreads();
    }

    const int er = lane >> 2;
    const int ec = (lane & 3) * 2;
#pragma unroll
    for (int mi = 0; mi < 4; mi++)
#pragma unroll
        for (int ni = 0; ni < 4; ni++) {
            const int r = m0 + warp_m * 64 + mi * 16 + er;
            const int c = n0 + warp_n * 32 + ni * 8 + ec;
            *(float2*)(out + (size_t)r * N + c) =
                make_float2(acc[mi][ni][0], acc[mi][ni][1]);
            *(float2*)(out + (size_t)(r + 8) * N + c) =
                make_float2(acc[mi][ni][2], acc[mi][ni][3]);
        }
}

// ===========================================================================
// Flash attention (causal). CTA = 128 q-rows x (b,h), 256 threads, 8 warps.
// 2 CTAs/SM. MMA ordering widened (hi,hi,lo,lo) + non-volatile mma.
// ===========================================================================
constexpr int FQT  = 128 * SASB;           // 18432 per 128-row Q tile
constexpr int FQHI = 0;
constexpr int FQLO = FQHI + FQT;           // 18432
constexpr int FKV0 = FQLO + FQT;           // 36864
constexpr int KVT  = 64 * SASB;            // 9216 per 64-row tile
constexpr int KVBUF = 2 * KVT;             // 18432 (K, V)
constexpr int FSM_TOTAL = FKV0 + 2 * KVBUF;  // 73728 (x2 CTAs = 144KB/SM)

__global__ __launch_bounds__(256, 2)
void flash_mma(const __half* __restrict__ Qh, const __half* __restrict__ Ql,
               const __half* __restrict__ Kv, const __half* __restrict__ Vv,
               __half* __restrict__ Xh, __half* __restrict__ Xl)
{
    extern __shared__ char smc[];
    const uint32_t sb = smem_u32(smc);
    const int tid  = threadIdx.x;
    const int wid  = tid >> 5;
    const int lane = tid & 31;
    const int qb   = gridDim.x - 1 - blockIdx.x;   // longest blocks first
    const int h    = blockIdx.y;
    const int b    = blockIdx.z;

    const size_t head = (size_t)b * S_LEN * D_DIM + (size_t)h * DKH;
    const int prow = tid >> 3;
    const int pch  = tid & 7;

    {
        const __half* qb_[2] = {Qh + head, Ql + head};
#pragma unroll
        for (int i = 0; i < 8; i++) {
            const int t   = i >> 2;
            const int row = ((i & 3) << 5) | prow;
            const void* src = qb_[t] + (size_t)(qb * 128 + row) * D_DIM + pch * 8;
            cpasync16(sb + t * FQT + row * SASB + pch * 16, src);
        }
    }

    const __half* kvb[2] = {Kv + head, Vv + head};
    auto produce_kv = [&](int kb) {
        const uint32_t bufb = sb + FKV0 + (kb & 1) * KVBUF;
#pragma unroll
        for (int i = 0; i < 4; i++) {
            const int t   = i >> 1;
            const int row = ((i & 1) << 5) | prow;
            const void* src = kvb[t] + (size_t)(kb * 64 + row) * D_DIM + pch * 8;
            cpasync16(bufb + t * KVT + row * SASB + pch * 16, src);
        }
    };

    produce_kv(0);
    cp_commit();

    float o[8][4];
    float m0r = -1e30f, m1r = -1e30f, l0r = 0.f, l1r = 0.f;
#pragma unroll
    for (int ni = 0; ni < 8; ni++)
#pragma unroll
        for (int q = 0; q < 4; q++) o[ni][q] = 0.f;

    const int lr  = lane & 15;
    const int lkb = (lane >> 4) << 4;
    const int kb_max = 2 * qb + 1;

    for (int kb = 0; kb <= kb_max; kb++) {
        if (kb < kb_max) {
            produce_kv(kb + 1);
            cp_commit();
            cp_wait1();
        } else {
            cp_wait0();
        }
        __syncthreads();

        const uint32_t kvbase = sb + FKV0 + (kb & 1) * KVBUF;

        float sc[8][4];
#pragma unroll
        for (int ni = 0; ni < 8; ni++)
#pragma unroll
            for (int q = 0; q < 4; q++) sc[ni][q] = 0.f;

#pragma unroll
        for (int ks = 0; ks < 4; ks++) {
            const uint32_t abyte = (wid * 16 + lr) * SASB + ks * 32 + lkb;
            uint32_t qh[4], ql[4];
            ldmx4(qh, sb + FQHI + abyte);
            ldmx4(ql, sb + FQLO + abyte);
#pragma unroll
            for (int nb = 0; nb < 4; nb++) {
                const uint32_t bbyte = (nb * 16 + lr) * SASB + ks * 32 + lkb;
                uint32_t kh[4];
                ldmx4(kh, kvbase + bbyte);
                // qh,qh then ql,ql: dependent pairs 2 apart + free scheduling
                mma16816(sc[nb * 2],     qh, kh[0], kh[2]);
                mma16816(sc[nb * 2 + 1], qh, kh[1], kh[3]);
                mma16816(sc[nb * 2],     ql, kh[0], kh[2]);
                mma16816(sc[nb * 2 + 1], ql, kh[1], kh[3]);
            }
        }

#pragma unroll
        for (int ni = 0; ni < 8; ni++)
#pragma unroll
            for (int q = 0; q < 4; q++) sc[ni][q] *= 0.125f;

        const int q0 = qb * 128 + wid * 16 + (lane >> 2);
        if (kb * 64 + 63 > qb * 128 + wid * 16) {
#pragma unroll
            for (int ni = 0; ni < 8; ni++) {
#pragma unroll
                for (int c = 0; c < 2; c++) {
                    const int col = kb * 64 + ni * 8 + (lane & 3) * 2 + c;
                    if (col > q0)     sc[ni][c]     = -1e30f;
                    if (col > q0 + 8) sc[ni][2 + c] = -1e30f;
                }
            }
        }

        float mx0 = -1e30f, mx1 = -1e30f;
#pragma unroll
        for (int ni = 0; ni < 8; ni++) {
            mx0 = fmaxf(mx0, fmaxf(sc[ni][0], sc[ni][1]));
            mx1 = fmaxf(mx1, fmaxf(sc[ni][2], sc[ni][3]));
        }
        mx0 = fmaxf(mx0, __shfl_xor_sync(0xffffffffu, mx0, 1));
        mx0 = fmaxf(mx0, __shfl_xor_sync(0xffffffffu, mx0, 2));
        mx1 = fmaxf(mx1, __shfl_xor_sync(0xffffffffu, mx1, 1));
        mx1 = fmaxf(mx1, __shfl_xor_sync(0xffffffffu, mx1, 2));

        const float mn0 = fmaxf(m0r, mx0);
        const float mn1 = fmaxf(m1r, mx1);
        const float al0 = __expf(m0r - mn0);
        const float al1 = __expf(m1r - mn1);
        m0r = mn0; m1r = mn1;

        float ls0 = 0.f, ls1 = 0.f;
#pragma unroll
        for (int ni = 0; ni < 8; ni++) {
            sc[ni][0] = __expf(sc[ni][0] - mn0); ls0 += sc[ni][0];
            sc[ni][1] = __expf(sc[ni][1] - mn0); ls0 += sc[ni][1];
            sc[ni][2] = __expf(sc[ni][2] - mn1); ls1 += sc[ni][2];
            sc[ni][3] = __expf(sc[ni][3] - mn1); ls1 += sc[ni][3];
        }
        ls0 += __shfl_xor_sync(0xffffffffu, ls0, 1);
        ls0 += __shfl_xor_sync(0xffffffffu, ls0, 2);
        ls1 += __shfl_xor_sync(0xffffffffu, ls1, 1);
        ls1 += __shfl_xor_sync(0xffffffffu, ls1, 2);
        l0r = l0r * al0 + ls0;
        l1r = l1r * al1 + ls1;
#pragma unroll
        for (int ni = 0; ni < 8; ni++) {
            o[ni][0] *= al0; o[ni][1] *= al0;
            o[ni][2] *= al1; o[ni][3] *= al1;
        }

#pragma unroll
        for (int ks = 0; ks < 4; ks++) {
            uint32_t ph[4], pl[4];
            split2h(sc[2 * ks][0],     sc[2 * ks][1],     ph[0], pl[0]);
            split2h(sc[2 * ks][2],     sc[2 * ks][3],     ph[1], pl[1]);
            split2h(sc[2 * ks + 1][0], sc[2 * ks + 1][1], ph[2], pl[2]);
            split2h(sc[2 * ks + 1][2], sc[2 * ks + 1][3], ph[3], pl[3]);
#pragma unroll
            for (int nt = 0; nt < 4; nt++) {
                const uint32_t vbyte =
                    (ks * 16 + ((lane >> 3) & 1) * 8 + (lane & 7)) * SASB +
                    nt * 32 + ((lane >> 4) << 4);
                uint32_t vh[4];
                ldmx4t(vh, kvbase + KVT + vbyte);
                // ph,ph then pl,pl: dependent pairs 2 apart + free scheduling
                mma16816(o[nt * 2],     ph, vh[0], vh[1]);
                mma16816(o[nt * 2 + 1], ph, vh[2], vh[3]);
                mma16816(o[nt * 2],     pl, vh[0], vh[1]);
                mma16816(o[nt * 2 + 1], pl, vh[2], vh[3]);
            }
        }
        __syncthreads();
    }

    const float inv0 = 1.f / l0r;
    const float inv1 = 1.f / l1r;
    const int r0 = qb * 128 + wid * 16 + (lane >> 2);
    const int ec = (lane & 3) * 2;
#pragma unroll
    for (int ni = 0; ni < 8; ni++) {
        const size_t c = head + (size_t)ni * 8 + ec;
        uint32_t hh, ll;
        split2h(o[ni][0] * inv0, o[ni][1] * inv0, hh, ll);
        *(uint32_t*)(Xh + c + (size_t)r0 * D_DIM) = hh;
        *(uint32_t*)(Xl + c + (size_t)r0 * D_DIM) = ll;
        split2h(o[ni][2] * inv1, o[ni][3] * inv1, hh, ll);
        *(uint32_t*)(Xh + c + (size_t)(r0 + 8) * D_DIM) = hh;
        *(uint32_t*)(Xl + c + (size_t)(r0 + 8) * D_DIM) = ll;
    }
}

// ---------------------------------------------------------------------------
// launch
// ---------------------------------------------------------------------------
extern "C" void kernel_launch(void* const* d_in, const int* in_sizes, int n_in,
                              void* d_out, int out_size)
{
    const float* query = (const float*)d_in[0];
    const float* key   = (const float*)d_in[1];
    const float* value = (const float*)d_in[2];
    const float* Wq    = (const float*)d_in[3];
    const float* Wk    = (const float*)d_in[4];
    const float* Wv    = (const float*)d_in[5];
    const float* Wo    = (const float*)d_in[6];
    float* out = (float*)d_out;

    __half *aQh, *aQl, *aKh, *aKl, *aVh, *aVl, *wq, *wk, *wv, *wo;
    __half *Qh, *Ql, *Kv, *Vv, *Xh, *Xl;
    cudaGetSymbolAddress((void**)&aQh, g_aQh); cudaGetSymbolAddress((void**)&aQl, g_aQl);
    cudaGetSymbolAddress((void**)&aKh, g_aKh); cudaGetSymbolAddress((void**)&aKl, g_aKl);
    cudaGetSymbolAddress((void**)&aVh, g_aVh); cudaGetSymbolAddress((void**)&aVl, g_aVl);
    cudaGetSymbolAddress((void**)&wq, g_wq);   cudaGetSymbolAddress((void**)&wk, g_wk);
    cudaGetSymbolAddress((void**)&wv, g_wv);   cudaGetSymbolAddress((void**)&wo, g_wo);
    cudaGetSymbolAddress((void**)&Qh, g_Qh);   cudaGetSymbolAddress((void**)&Ql, g_Ql);
    cudaGetSymbolAddress((void**)&Kv, g_Kv);   cudaGetSymbolAddress((void**)&Vv, g_Vv);
    cudaGetSymbolAddress((void**)&Xh, g_Xh);   cudaGetSymbolAddress((void**)&Xl, g_Xl);

    cudaFuncSetAttribute(gemm_proj, cudaFuncAttributeMaxDynamicSharedMemorySize,
                         SM_GEMM_TOTAL);
    cudaFuncSetAttribute(gemm_out, cudaFuncAttributeMaxDynamicSharedMemorySize,
                         SM_GEMM_TOTAL);
    cudaFuncSetAttribute(flash_mma, cudaFuncAttributeMaxDynamicSharedMemorySize,
                         FSM_TOTAL);

    dim3 cgrid(256, 1, 7);
    convert_all<<<cgrid, 256>>>((const float4*)query, (const float4*)key,
                                (const float4*)value, (const float4*)Wq,
                                (const float4*)Wk, (const float4*)Wv,
                                (const float4*)Wo,
                                (uint2*)aQh, (uint2*)aQl, (uint2*)aKh, (uint2*)aKl,
                                (uint2*)aVh, (uint2*)aVl,
                                (uint2*)wq, (uint2*)wk, (uint2*)wv, (uint2*)wo);

    dim3 pgrid(D_DIM / 128, MTOT / 128, 3);   // (8, 32, 3)
    gemm_proj<<<pgrid, 256, SM_GEMM_TOTAL>>>(aQh, aQl, aKh, aKl, aVh, aVl,
                                             wq, wk, wv, Qh, Ql, Kv, Vv);

    dim3 fgrid(S_LEN / 128, H_NUM, B_SZ);     // (16, 16, 2)
    flash_mma<<<fgrid, 256, FSM_TOTAL>>>(Qh, Ql, Kv, Vv, Xh, Xl);

    dim3 ogrid(D_DIM / 128, MTOT / 128);      // (8, 32)
    gemm_out<<<ogrid, 256, SM_GEMM_TOTAL>>>(Xh, Xl, wo, out);
}

// round 14
// speedup vs baseline: 1.7609x; 1.1292x over previous
#include <cuda_runtime.h>
#include <cuda_fp16.h>
#include <math.h>
#include <stdint.h>

#define B_SZ  2
#define S_LEN 2048
#define D_DIM 1024
#define H_NUM 16
#define DKH   64
#define MTOT  (B_SZ * S_LEN)          // 4096

// ---------------------------------------------------------------------------
// Scratch (allocation-free rule: __device__ globals). fp16 operands.
// ---------------------------------------------------------------------------
__device__ __half g_aQh[MTOT * D_DIM], g_aQl[MTOT * D_DIM];  // split(query)
__device__ __half g_aKh[MTOT * D_DIM], g_aKl[MTOT * D_DIM];  // split(key)
__device__ __half g_aVh[MTOT * D_DIM], g_aVl[MTOT * D_DIM];  // split(value)
__device__ __half g_wq[D_DIM * D_DIM], g_wk[D_DIM * D_DIM];  // weights fp16
__device__ __half g_wv[D_DIM * D_DIM], g_wo[D_DIM * D_DIM];
__device__ __half g_Qv[MTOT * D_DIM];                        // Q proj (single)
__device__ __half g_Kv[MTOT * D_DIM];                        // K proj (single)
__device__ __half g_Vv[MTOT * D_DIM];                        // V proj (single)
__device__ __half g_Xh[MTOT * D_DIM], g_Xl[MTOT * D_DIM];    // attn out (split)

// ===========================================================================
// helpers
// ===========================================================================
__device__ __forceinline__ uint32_t smem_u32(const void* p) {
    uint32_t a;
    asm("{ .reg .u64 t; cvta.to.shared.u64 t, %1; cvt.u32.u64 %0, t; }"
        : "=r"(a) : "l"(p));
    return a;
}
__device__ __forceinline__ void ldmx4(uint32_t* r, uint32_t addr) {
    asm volatile("ldmatrix.sync.aligned.m8n8.x4.shared.b16 {%0,%1,%2,%3}, [%4];"
                 : "=r"(r[0]), "=r"(r[1]), "=r"(r[2]), "=r"(r[3]) : "r"(addr));
}
__device__ __forceinline__ void ldmx4t(uint32_t* r, uint32_t addr) {
    asm volatile("ldmatrix.sync.aligned.m8n8.x4.trans.shared.b16 {%0,%1,%2,%3}, [%4];"
                 : "=r"(r[0]), "=r"(r[1]), "=r"(r[2]), "=r"(r[3]) : "r"(addr));
}
__device__ __forceinline__ void mma16816(float* c, const uint32_t* a,
                                         uint32_t b0, uint32_t b1) {
    asm("mma.sync.aligned.m16n8k16.row.col.f32.f16.f16.f32 "
        "{%0,%1,%2,%3}, {%4,%5,%6,%7}, {%8,%9}, {%0,%1,%2,%3};"
        : "+f"(c[0]), "+f"(c[1]), "+f"(c[2]), "+f"(c[3])
        : "r"(a[0]), "r"(a[1]), "r"(a[2]), "r"(a[3]), "r"(b0), "r"(b1));
}
__device__ __forceinline__ uint32_t packh(float x, float y) {
    __half2 h = __float22half2_rn(make_float2(x, y));
    return *(uint32_t*)&h;
}
__device__ __forceinline__ void split2h(float x, float y, uint32_t& h, uint32_t& l) {
    h = packh(x, y);
    __half2 t = *(__half2*)&h;
    float2 f = __half22float2(t);
    l = packh(x - f.x, y - f.y);
}
__device__ __forceinline__ void cpasync16(uint32_t dst, const void* src) {
    asm volatile("cp.async.cg.shared.global [%0], [%1], 16;"
                 :: "r"(dst), "l"(src));
}
__device__ __forceinline__ void cp_commit() {
    asm volatile("cp.async.commit_group;" ::: "memory");
}
__device__ __forceinline__ void cp_wait0() {
    asm volatile("cp.async.wait_group 0;" ::: "memory");
}
__device__ __forceinline__ void cp_wait1() {
    asm volatile("cp.async.wait_group 1;" ::: "memory");
}

// ===========================================================================
// convert_all: z=0..2 split activations, z=3..6 convert weights (grid-stride)
// ===========================================================================
__global__ void convert_all(const float4* __restrict__ q, const float4* __restrict__ k,
                            const float4* __restrict__ v,
                            const float4* __restrict__ wq, const float4* __restrict__ wk,
                            const float4* __restrict__ wv, const float4* __restrict__ wo,
                            uint2* __restrict__ aqh, uint2* __restrict__ aql,
                            uint2* __restrict__ akh, uint2* __restrict__ akl,
                            uint2* __restrict__ avh, uint2* __restrict__ avl,
                            uint2* __restrict__ owq, uint2* __restrict__ owk,
                            uint2* __restrict__ owv, uint2* __restrict__ owo)
{
    const int z = blockIdx.z;
    const int stride = gridDim.x * blockDim.x;
    if (z < 3) {
        const float4* src = (z == 0) ? q : (z == 1) ? k : v;
        uint2* hi = (z == 0) ? aqh : (z == 1) ? akh : avh;
        uint2* lo = (z == 0) ? aql : (z == 1) ? akl : avl;
        const int n4 = MTOT * D_DIM / 4;
        for (int i = blockIdx.x * blockDim.x + threadIdx.x; i < n4; i += stride) {
            const float4 w = src[i];
            uint2 uh, ul;
            split2h(w.x, w.y, uh.x, ul.x);
            split2h(w.z, w.w, uh.y, ul.y);
            hi[i] = uh;
            lo[i] = ul;
        }
    } else {
        const float4* src = (z == 3) ? wq : (z == 4) ? wk : (z == 5) ? wv : wo;
        uint2* dst = (z == 3) ? owq : (z == 4) ? owk : (z == 5) ? owv : owo;
        const int n4 = D_DIM * D_DIM / 4;
        for (int i = blockIdx.x * blockDim.x + threadIdx.x; i < n4; i += stride) {
            const float4 w = src[i];
            dst[i] = make_uint2(packh(w.x, w.y), packh(w.z, w.w));
        }
    }
}

// ===========================================================================
// GEMM geometry: CTA tile 128x128, 256 threads = 8 warps (2m x 4n),
// warp tile 64x32 (acc 4x4 m16n8). K staged 64 fp16, cp.async double-buffer.
// 2 CTAs / SM.
// ===========================================================================
constexpr int SASB   = 144;                // padded row bytes (64 fp16 + pad)
constexpr int GT     = 128 * SASB;         // 18432 per 128-row tile
constexpr int GSTAGE = 3 * GT;             // 55296 per stage (Ahi, Alo, B)
constexpr int SM_GEMM_TOTAL = 2 * GSTAGE;  // 110592 (x2 CTAs = 216KB/SM)
constexpr int STAGES = D_DIM / 64;         // 16

__device__ __forceinline__ void gemm_stage_compute(
    uint32_t bufb, int warp_m, int warp_n, int lr, int lkb, float acc[4][4][4])
{
#pragma unroll
    for (int ks = 0; ks < 4; ks++) {
        const uint32_t kb = ks * 32 + lkb;
        uint32_t ah[4][4], al[4][4];
#pragma unroll
        for (int mi = 0; mi < 4; mi++) {
            const uint32_t byte = (warp_m * 64 + mi * 16 + lr) * SASB + kb;
            ldmx4(ah[mi], bufb + byte);
            ldmx4(al[mi], bufb + GT + byte);
        }
        uint32_t bh[4][2];
#pragma unroll
        for (int nb = 0; nb < 2; nb++) {
            const uint32_t byte = (warp_n * 32 + nb * 16 + lr) * SASB + kb;
            uint32_t r[4];
            ldmx4(r, bufb + 2 * GT + byte);
            bh[nb * 2][0] = r[0]; bh[nb * 2 + 1][0] = r[1];
            bh[nb * 2][1] = r[2]; bh[nb * 2 + 1][1] = r[3];
        }
#pragma unroll
        for (int mi = 0; mi < 4; mi++)
#pragma unroll
            for (int ni = 0; ni < 4; ni++)
                mma16816(acc[mi][ni], ah[mi], bh[ni][0], bh[ni][1]);
#pragma unroll
        for (int mi = 0; mi < 4; mi++)
#pragma unroll
            for (int ni = 0; ni < 4; ni++)
                mma16816(acc[mi][ni], al[mi], bh[ni][0], bh[ni][1]);
    }
}

// producer: 12 cp.async per thread per stage (3 tiles x 1024 16B-chunks)
__device__ __forceinline__ void gemm_produce(
    uint32_t sb, int s, const __half* Ahb, const __half* Alb, const __half* Bb,
    int tid)
{
    const uint32_t bufb = sb + (s & 1) * GSTAGE;
#pragma unroll
    for (int i = 0; i < 12; i++) {
        const int c = i * 256 + tid;          // 0..3071
        const int t = c >> 10;                // tile 0..2
        const int w = c & 1023;
        const int row = w >> 3, ch = w & 7;
        const __half* src = (t == 0) ? Ahb : (t == 1) ? Alb : Bb;
        cpasync16(bufb + t * GT + row * SASB + ch * 16,
                  src + (size_t)row * D_DIM + s * 64 + ch * 8);
    }
}

// ===========================================================================
// gemm_proj: z=0/1/2 -> Q/K/V, all single-fp16 outputs now.
// ===========================================================================
__global__ __launch_bounds__(256, 2)
void gemm_proj(const __half* __restrict__ aQh, const __half* __restrict__ aQl,
               const __half* __restrict__ aKh, const __half* __restrict__ aKl,
               const __half* __restrict__ aVh, const __half* __restrict__ aVl,
               const __half* __restrict__ wq, const __half* __restrict__ wk,
               const __half* __restrict__ wv,
               __half* __restrict__ Qv, __half* __restrict__ Kv,
               __half* __restrict__ Vv)
{
    extern __shared__ char smc[];
    const uint32_t sb = smem_u32(smc);
    const int tid  = threadIdx.x;
    const int wid  = tid >> 5;
    const int lane = tid & 31;
    const int warp_m = wid & 1;
    const int warp_n = wid >> 1;
    const int m0 = blockIdx.y * 128;
    const int n0 = blockIdx.x * 128;
    const int z  = blockIdx.z;
    const int N  = D_DIM;

    const __half* Ahb = ((z == 0) ? aQh : (z == 1) ? aKh : aVh) + (size_t)m0 * D_DIM;
    const __half* Alb = ((z == 0) ? aQl : (z == 1) ? aKl : aVl) + (size_t)m0 * D_DIM;
    const __half* Bb  = ((z == 0) ? wq  : (z == 1) ? wk  : wv)  + (size_t)n0 * D_DIM;

    float acc[4][4][4];
#pragma unroll
    for (int mi = 0; mi < 4; mi++)
#pragma unroll
        for (int ni = 0; ni < 4; ni++)
#pragma unroll
            for (int q = 0; q < 4; q++) acc[mi][ni][q] = 0.f;

    const int lr  = lane & 15;
    const int lkb = (lane >> 4) << 4;

    gemm_produce(sb, 0, Ahb, Alb, Bb, tid);
    cp_commit();

    for (int s = 0; s < STAGES; s++) {
        if (s + 1 < STAGES) {
            gemm_produce(sb, s + 1, Ahb, Alb, Bb, tid);
            cp_commit();
            cp_wait1();
        } else {
            cp_wait0();
        }
        __syncthreads();
        gemm_stage_compute(sb + (s & 1) * GSTAGE, warp_m, warp_n, lr, lkb, acc);
        __syncthreads();
    }

    const int er = lane >> 2;
    const int ec = (lane & 3) * 2;
    __half* C = (z == 0) ? Qv : (z == 1) ? Kv : Vv;
#pragma unroll
    for (int mi = 0; mi < 4; mi++)
#pragma unroll
        for (int ni = 0; ni < 4; ni++) {
            const int r = m0 + warp_m * 64 + mi * 16 + er;
            const int c = n0 + warp_n * 32 + ni * 8 + ec;
            *(uint32_t*)(C + (size_t)r * N + c) =
                packh(acc[mi][ni][0], acc[mi][ni][1]);
            *(uint32_t*)(C + (size_t)(r + 8) * N + c) =
                packh(acc[mi][ni][2], acc[mi][ni][3]);
        }
}

// ===========================================================================
// gemm_out: out = X @ Wo^T (f32 out). X split fp16, Wo single.
// ===========================================================================
__global__ __launch_bounds__(256, 2)
void gemm_out(const __half* __restrict__ Xh, const __half* __restrict__ Xl,
              const __half* __restrict__ wo, float* __restrict__ out)
{
    extern __shared__ char smc[];
    const uint32_t sb = smem_u32(smc);
    const int tid  = threadIdx.x;
    const int wid  = tid >> 5;
    const int lane = tid & 31;
    const int warp_m = wid & 1;
    const int warp_n = wid >> 1;
    const int m0 = blockIdx.y * 128;
    const int n0 = blockIdx.x * 128;
    const int N  = D_DIM;

    const __half* Ahb = Xh + (size_t)m0 * D_DIM;
    const __half* Alb = Xl + (size_t)m0 * D_DIM;
    const __half* Bb  = wo + (size_t)n0 * D_DIM;

    float acc[4][4][4];
#pragma unroll
    for (int mi = 0; mi < 4; mi++)
#pragma unroll
        for (int ni = 0; ni < 4; ni++)
#pragma unroll
            for (int q = 0; q < 4; q++) acc[mi][ni][q] = 0.f;

    const int lr  = lane & 15;
    const int lkb = (lane >> 4) << 4;

    gemm_produce(sb, 0, Ahb, Alb, Bb, tid);
    cp_commit();

    for (int s = 0; s < STAGES; s++) {
        if (s + 1 < STAGES) {
            gemm_produce(sb, s + 1, Ahb, Alb, Bb, tid);
            cp_commit();
            cp_wait1();
        } else {
            cp_wait0();
        }
        __syncthreads();
        gemm_stage_compute(sb + (s & 1) * GSTAGE, warp_m, warp_n, lr, lkb, acc);
        __syncthreads();
    }

    const int er = lane >> 2;
    const int ec = (lane & 3) * 2;
#pragma unroll
    for (int mi = 0; mi < 4; mi++)
#pragma unroll
        for (int ni = 0; ni < 4; ni++) {
            const int r = m0 + warp_m * 64 + mi * 16 + er;
            const int c = n0 + warp_n * 32 + ni * 8 + ec;
            *(float2*)(out + (size_t)r * N + c) =
                make_float2(acc[mi][ni][0], acc[mi][ni][1]);
            *(float2*)(out + (size_t)(r + 8) * N + c) =
                make_float2(acc[mi][ni][2], acc[mi][ni][3]);
        }
}

// ===========================================================================
// Flash attention (causal). CTA = 128 q-rows x (b,h), 256 threads, 8 warps.
// Q, K, V, P all single fp16 (error budget verified by K/V precedent).
// Half the MMAs of the split version. 2 CTAs/SM.
// ===========================================================================
constexpr int FQT  = 128 * SASB;           // 18432: single Q tile
constexpr int FKV0 = FQT;                  // 18432
constexpr int KVT  = 64 * SASB;            // 9216 per 64-row tile
constexpr int KVBUF = 2 * KVT;             // 18432 (K, V)
constexpr int FSM_TOTAL = FKV0 + 2 * KVBUF;  // 55296 (x2 CTAs = 108KB/SM)

__global__ __launch_bounds__(256, 2)
void flash_mma(const __half* __restrict__ Qv, const __half* __restrict__ Kv,
               const __half* __restrict__ Vv,
               __half* __restrict__ Xh, __half* __restrict__ Xl)
{
    extern __shared__ char smc[];
    const uint32_t sb = smem_u32(smc);
    const int tid  = threadIdx.x;
    const int wid  = tid >> 5;
    const int lane = tid & 31;
    const int qb   = gridDim.x - 1 - blockIdx.x;   // longest blocks first
    const int h    = blockIdx.y;
    const int b    = blockIdx.z;

    const size_t head = (size_t)b * S_LEN * D_DIM + (size_t)h * DKH;
    const int prow = tid >> 3;
    const int pch  = tid & 7;

    { // Q tile (single): 4 cp.async per thread
#pragma unroll
        for (int i = 0; i < 4; i++) {
            const int row = (i << 5) | prow;
            const void* src = Qv + head + (size_t)(qb * 128 + row) * D_DIM + pch * 8;
            cpasync16(sb + row * SASB + pch * 16, src);
        }
    }

    const __half* kvb[2] = {Kv + head, Vv + head};
    auto produce_kv = [&](int kb) {
        const uint32_t bufb = sb + FKV0 + (kb & 1) * KVBUF;
#pragma unroll
        for (int i = 0; i < 4; i++) {
            const int t   = i >> 1;
            const int row = ((i & 1) << 5) | prow;
            const void* src = kvb[t] + (size_t)(kb * 64 + row) * D_DIM + pch * 8;
            cpasync16(bufb + t * KVT + row * SASB + pch * 16, src);
        }
    };

    produce_kv(0);
    cp_commit();

    float o[8][4];
    float m0r = -1e30f, m1r = -1e30f, l0r = 0.f, l1r = 0.f;
#pragma unroll
    for (int ni = 0; ni < 8; ni++)
#pragma unroll
        for (int q = 0; q < 4; q++) o[ni][q] = 0.f;

    const int lr  = lane & 15;
    const int lkb = (lane >> 4) << 4;
    const int kb_max = 2 * qb + 1;

    for (int kb = 0; kb <= kb_max; kb++) {
        if (kb < kb_max) {
            produce_kv(kb + 1);
            cp_commit();
            cp_wait1();
        } else {
            cp_wait0();
        }
        __syncthreads();

        const uint32_t kvbase = sb + FKV0 + (kb & 1) * KVBUF;

        // ---- QK^T (single-precision operands: 2 MMAs per 16x16 tile) ----
        float sc[8][4];
#pragma unroll
        for (int ni = 0; ni < 8; ni++)
#pragma unroll
            for (int q = 0; q < 4; q++) sc[ni][q] = 0.f;

#pragma unroll
        for (int ks = 0; ks < 4; ks++) {
            const uint32_t abyte = (wid * 16 + lr) * SASB + ks * 32 + lkb;
            uint32_t qh[4];
            ldmx4(qh, sb + abyte);
#pragma unroll
            for (int nb = 0; nb < 4; nb++) {
                const uint32_t bbyte = (nb * 16 + lr) * SASB + ks * 32 + lkb;
                uint32_t kh[4];
                ldmx4(kh, kvbase + bbyte);
                mma16816(sc[nb * 2],     qh, kh[0], kh[2]);
                mma16816(sc[nb * 2 + 1], qh, kh[1], kh[3]);
            }
        }

#pragma unroll
        for (int ni = 0; ni < 8; ni++)
#pragma unroll
            for (int q = 0; q < 4; q++) sc[ni][q] *= 0.125f;

        const int q0 = qb * 128 + wid * 16 + (lane >> 2);
        if (kb * 64 + 63 > qb * 128 + wid * 16) {
#pragma unroll
            for (int ni = 0; ni < 8; ni++) {
#pragma unroll
                for (int c = 0; c < 2; c++) {
                    const int col = kb * 64 + ni * 8 + (lane & 3) * 2 + c;
                    if (col > q0)     sc[ni][c]     = -1e30f;
                    if (col > q0 + 8) sc[ni][2 + c] = -1e30f;
                }
            }
        }

        float mx0 = -1e30f, mx1 = -1e30f;
#pragma unroll
        for (int ni = 0; ni < 8; ni++) {
            mx0 = fmaxf(mx0, fmaxf(sc[ni][0], sc[ni][1]));
            mx1 = fmaxf(mx1, fmaxf(sc[ni][2], sc[ni][3]));
        }
        mx0 = fmaxf(mx0, __shfl_xor_sync(0xffffffffu, mx0, 1));
        mx0 = fmaxf(mx0, __shfl_xor_sync(0xffffffffu, mx0, 2));
        mx1 = fmaxf(mx1, __shfl_xor_sync(0xffffffffu, mx1, 1));
        mx1 = fmaxf(mx1, __shfl_xor_sync(0xffffffffu, mx1, 2));

        const float mn0 = fmaxf(m0r, mx0);
        const float mn1 = fmaxf(m1r, mx1);
        const float al0 = __expf(m0r - mn0);
        const float al1 = __expf(m1r - mn1);
        m0r = mn0; m1r = mn1;

        float ls0 = 0.f, ls1 = 0.f;
#pragma unroll
        for (int ni = 0; ni < 8; ni++) {
            sc[ni][0] = __expf(sc[ni][0] - mn0); ls0 += sc[ni][0];
            sc[ni][1] = __expf(sc[ni][1] - mn0); ls0 += sc[ni][1];
            sc[ni][2] = __expf(sc[ni][2] - mn1); ls1 += sc[ni][2];
            sc[ni][3] = __expf(sc[ni][3] - mn1); ls1 += sc[ni][3];
        }
        ls0 += __shfl_xor_sync(0xffffffffu, ls0, 1);
        ls0 += __shfl_xor_sync(0xffffffffu, ls0, 2);
        ls1 += __shfl_xor_sync(0xffffffffu, ls1, 1);
        ls1 += __shfl_xor_sync(0xffffffffu, ls1, 2);
        l0r = l0r * al0 + ls0;
        l1r = l1r * al1 + ls1;
#pragma unroll
        for (int ni = 0; ni < 8; ni++) {
            o[ni][0] *= al0; o[ni][1] *= al0;
            o[ni][2] *= al1; o[ni][3] *= al1;
        }

        // ---- P.V (single fp16 P: 2 MMAs per 16x16 tile) ----
#pragma unroll
        for (int ks = 0; ks < 4; ks++) {
            uint32_t ph[4];
            ph[0] = packh(sc[2 * ks][0],     sc[2 * ks][1]);
            ph[1] = packh(sc[2 * ks][2],     sc[2 * ks][3]);
            ph[2] = packh(sc[2 * ks + 1][0], sc[2 * ks + 1][1]);
            ph[3] = packh(sc[2 * ks + 1][2], sc[2 * ks + 1][3]);
#pragma unroll
            for (int nt = 0; nt < 4; nt++) {
                const uint32_t vbyte =
                    (ks * 16 + ((lane >> 3) & 1) * 8 + (lane & 7)) * SASB +
                    nt * 32 + ((lane >> 4) << 4);
                uint32_t vh[4];
                ldmx4t(vh, kvbase + KVT + vbyte);
                mma16816(o[nt * 2],     ph, vh[0], vh[1]);
                mma16816(o[nt * 2 + 1], ph, vh[2], vh[3]);
            }
        }
        __syncthreads();
    }

    const float inv0 = 1.f / l0r;
    const float inv1 = 1.f / l1r;
    const int r0 = qb * 128 + wid * 16 + (lane >> 2);
    const int ec = (lane & 3) * 2;
#pragma unroll
    for (int ni = 0; ni < 8; ni++) {
        const size_t c = head + (size_t)ni * 8 + ec;
        uint32_t hh, ll;
        split2h(o[ni][0] * inv0, o[ni][1] * inv0, hh, ll);
        *(uint32_t*)(Xh + c + (size_t)r0 * D_DIM) = hh;
        *(uint32_t*)(Xl + c + (size_t)r0 * D_DIM) = ll;
        split2h(o[ni][2] * inv1, o[ni][3] * inv1, hh, ll);
        *(uint32_t*)(Xh + c + (size_t)(r0 + 8) * D_DIM) = hh;
        *(uint32_t*)(Xl + c + (size_t)(r0 + 8) * D_DIM) = ll;
    }
}

// ---------------------------------------------------------------------------
// launch
// ---------------------------------------------------------------------------
extern "C" void kernel_launch(void* const* d_in, const int* in_sizes, int n_in,
                              void* d_out, int out_size)
{
    const float* query = (const float*)d_in[0];
    const float* key   = (const float*)d_in[1];
    const float* value = (const float*)d_in[2];
    const float* Wq    = (const float*)d_in[3];
    const float* Wk    = (const float*)d_in[4];
    const float* Wv    = (const float*)d_in[5];
    const float* Wo    = (const float*)d_in[6];
    float* out = (float*)d_out;

    __half *aQh, *aQl, *aKh, *aKl, *aVh, *aVl, *wq, *wk, *wv, *wo;
    __half *Qv, *Kv, *Vv, *Xh, *Xl;
    cudaGetSymbolAddress((void**)&aQh, g_aQh); cudaGetSymbolAddress((void**)&aQl, g_aQl);
    cudaGetSymbolAddress((void**)&aKh, g_aKh); cudaGetSymbolAddress((void**)&aKl, g_aKl);
    cudaGetSymbolAddress((void**)&aVh, g_aVh); cudaGetSymbolAddress((void**)&aVl, g_aVl);
    cudaGetSymbolAddress((void**)&wq, g_wq);   cudaGetSymbolAddress((void**)&wk, g_wk);
    cudaGetSymbolAddress((void**)&wv, g_wv);   cudaGetSymbolAddress((void**)&wo, g_wo);
    cudaGetSymbolAddress((void**)&Qv, g_Qv);
    cudaGetSymbolAddress((void**)&Kv, g_Kv);   cudaGetSymbolAddress((void**)&Vv, g_Vv);
    cudaGetSymbolAddress((void**)&Xh, g_Xh);   cudaGetSymbolAddress((void**)&Xl, g_Xl);

    cudaFuncSetAttribute(gemm_proj, cudaFuncAttributeMaxDynamicSharedMemorySize,
                         SM_GEMM_TOTAL);
    cudaFuncSetAttribute(gemm_out, cudaFuncAttributeMaxDynamicSharedMemorySize,
                         SM_GEMM_TOTAL);
    cudaFuncSetAttribute(flash_mma, cudaFuncAttributeMaxDynamicSharedMemorySize,
                         FSM_TOTAL);

    dim3 cgrid(256, 1, 7);
    convert_all<<<cgrid, 256>>>((const float4*)query, (const float4*)key,
                                (const float4*)value, (const float4*)Wq,
                                (const float4*)Wk, (const float4*)Wv,
                                (const float4*)Wo,
                                (uint2*)aQh, (uint2*)aQl, (uint2*)aKh, (uint2*)aKl,
                                (uint2*)aVh, (uint2*)aVl,
                                (uint2*)wq, (uint2*)wk, (uint2*)wv, (uint2*)wo);

    dim3 pgrid(D_DIM / 128, MTOT / 128, 3);   // (8, 32, 3)
    gemm_proj<<<pgrid, 256, SM_GEMM_TOTAL>>>(aQh, aQl, aKh, aKl, aVh, aVl,
                                             wq, wk, wv, Qv, Kv, Vv);

    dim3 fgrid(S_LEN / 128, H_NUM, B_SZ);     // (16, 16, 2)
    flash_mma<<<fgrid, 256, FSM_TOTAL>>>(Qv, Kv, Vv, Xh, Xl);

    dim3 ogrid(D_DIM / 128, MTOT / 128);      // (8, 32)
    gemm_out<<<ogrid, 256, SM_GEMM_TOTAL>>>(Xh, Xl, wo, out);
}

// round 15
// speedup vs baseline: 2.5527x; 1.4497x over previous
#include <cuda_runtime.h>
#include <cuda_fp16.h>
#include <math.h>
#include <stdint.h>

#define B_SZ  2
#define S_LEN 2048
#define D_DIM 1024
#define H_NUM 16
#define DKH   64
#define MTOT  (B_SZ * S_LEN)          // 4096

// ---------------------------------------------------------------------------
// Scratch (allocation-free rule: __device__ globals). All single fp16 now.
// ---------------------------------------------------------------------------
__device__ __half g_aQ[MTOT * D_DIM], g_aK[MTOT * D_DIM], g_aV[MTOT * D_DIM];
__device__ __half g_wq[D_DIM * D_DIM], g_wk[D_DIM * D_DIM];
__device__ __half g_wv[D_DIM * D_DIM], g_wo[D_DIM * D_DIM];
__device__ __half g_Qv[MTOT * D_DIM], g_Kv[MTOT * D_DIM], g_Vv[MTOT * D_DIM];
__device__ __half g_Xv[MTOT * D_DIM];                      // attn out (single)

// ===========================================================================
// helpers
// ===========================================================================
__device__ __forceinline__ uint32_t smem_u32(const void* p) {
    uint32_t a;
    asm("{ .reg .u64 t; cvta.to.shared.u64 t, %1; cvt.u32.u64 %0, t; }"
        : "=r"(a) : "l"(p));
    return a;
}
__device__ __forceinline__ void ldmx4(uint32_t* r, uint32_t addr) {
    asm volatile("ldmatrix.sync.aligned.m8n8.x4.shared.b16 {%0,%1,%2,%3}, [%4];"
                 : "=r"(r[0]), "=r"(r[1]), "=r"(r[2]), "=r"(r[3]) : "r"(addr));
}
__device__ __forceinline__ void ldmx4t(uint32_t* r, uint32_t addr) {
    asm volatile("ldmatrix.sync.aligned.m8n8.x4.trans.shared.b16 {%0,%1,%2,%3}, [%4];"
                 : "=r"(r[0]), "=r"(r[1]), "=r"(r[2]), "=r"(r[3]) : "r"(addr));
}
__device__ __forceinline__ void mma16816(float* c, const uint32_t* a,
                                         uint32_t b0, uint32_t b1) {
    asm("mma.sync.aligned.m16n8k16.row.col.f32.f16.f16.f32 "
        "{%0,%1,%2,%3}, {%4,%5,%6,%7}, {%8,%9}, {%0,%1,%2,%3};"
        : "+f"(c[0]), "+f"(c[1]), "+f"(c[2]), "+f"(c[3])
        : "r"(a[0]), "r"(a[1]), "r"(a[2]), "r"(a[3]), "r"(b0), "r"(b1));
}
__device__ __forceinline__ uint32_t packh(float x, float y) {
    __half2 h = __float22half2_rn(make_float2(x, y));
    return *(uint32_t*)&h;
}
__device__ __forceinline__ void cpasync16(uint32_t dst, const void* src) {
    asm volatile("cp.async.cg.shared.global [%0], [%1], 16;"
                 :: "r"(dst), "l"(src));
}
__device__ __forceinline__ void cp_commit() {
    asm volatile("cp.async.commit_group;" ::: "memory");
}
__device__ __forceinline__ void cp_wait0() {
    asm volatile("cp.async.wait_group 0;" ::: "memory");
}
__device__ __forceinline__ void cp_wait1() {
    asm volatile("cp.async.wait_group 1;" ::: "memory");
}

// ===========================================================================
// convert_all: z=0..6 -> single fp16 convert of q,k,v,Wq,Wk,Wv,Wo
// ===========================================================================
__global__ void convert_all(const float4* __restrict__ q, const float4* __restrict__ k,
                            const float4* __restrict__ v,
                            const float4* __restrict__ wq, const float4* __restrict__ wk,
                            const float4* __restrict__ wv, const float4* __restrict__ wo,
                            uint2* __restrict__ oq, uint2* __restrict__ ok,
                            uint2* __restrict__ ov,
                            uint2* __restrict__ owq, uint2* __restrict__ owk,
                            uint2* __restrict__ owv, uint2* __restrict__ owo)
{
    const int z = blockIdx.z;
    const int stride = gridDim.x * blockDim.x;
    const float4* src = (z == 0) ? q : (z == 1) ? k : (z == 2) ? v :
                        (z == 3) ? wq : (z == 4) ? wk : (z == 5) ? wv : wo;
    uint2* dst = (z == 0) ? oq : (z == 1) ? ok : (z == 2) ? ov :
                 (z == 3) ? owq : (z == 4) ? owk : (z == 5) ? owv : owo;
    const int n4 = ((z < 3) ? MTOT * D_DIM : D_DIM * D_DIM) / 4;
    for (int i = blockIdx.x * blockDim.x + threadIdx.x; i < n4; i += stride) {
        const float4 w = src[i];
        dst[i] = make_uint2(packh(w.x, w.y), packh(w.z, w.w));
    }
}

// ===========================================================================
// GEMM geometry: CTA tile 128x128, 256 threads = 8 warps (2m x 4n),
// warp tile 64x32 (acc 4x4 m16n8). Single x single fp16: 16 MMAs per ks.
// K staged 64 fp16, cp.async double-buffer, 2 CTAs/SM.
// ===========================================================================
constexpr int SASB   = 144;                // padded row bytes (64 fp16 + pad)
constexpr int GT     = 128 * SASB;         // 18432 per 128-row tile
constexpr int GSTAGE = 2 * GT;             // 36864 per stage (A, B)
constexpr int SM_GEMM_TOTAL = 2 * GSTAGE;  // 73728 (x2 CTAs = 144KB/SM)
constexpr int STAGES = D_DIM / 64;         // 16

__device__ __forceinline__ void gemm_stage_compute(
    uint32_t bufb, int warp_m, int warp_n, int lr, int lkb, float acc[4][4][4])
{
#pragma unroll
    for (int ks = 0; ks < 4; ks++) {
        const uint32_t kb = ks * 32 + lkb;
        uint32_t ah[4][4];
#pragma unroll
        for (int mi = 0; mi < 4; mi++) {
            const uint32_t byte = (warp_m * 64 + mi * 16 + lr) * SASB + kb;
            ldmx4(ah[mi], bufb + byte);
        }
        uint32_t bh[4][2];
#pragma unroll
        for (int nb = 0; nb < 2; nb++) {
            const uint32_t byte = (warp_n * 32 + nb * 16 + lr) * SASB + kb;
            uint32_t r[4];
            ldmx4(r, bufb + GT + byte);
            bh[nb * 2][0] = r[0]; bh[nb * 2 + 1][0] = r[1];
            bh[nb * 2][1] = r[2]; bh[nb * 2 + 1][1] = r[3];
        }
#pragma unroll
        for (int mi = 0; mi < 4; mi++)
#pragma unroll
            for (int ni = 0; ni < 4; ni++)
                mma16816(acc[mi][ni], ah[mi], bh[ni][0], bh[ni][1]);
    }
}

// producer: 8 cp.async per thread per stage (2 tiles x 1024 16B-chunks)
__device__ __forceinline__ void gemm_produce(
    uint32_t sb, int s, const __half* Ab, const __half* Bb, int tid)
{
    const uint32_t bufb = sb + (s & 1) * GSTAGE;
#pragma unroll
    for (int i = 0; i < 8; i++) {
        const int c = i * 256 + tid;          // 0..2047
        const int t = c >> 10;                // tile 0..1
        const int w = c & 1023;
        const int row = w >> 3, ch = w & 7;
        const __half* src = (t == 0) ? Ab : Bb;
        cpasync16(bufb + t * GT + row * SASB + ch * 16,
                  src + (size_t)row * D_DIM + s * 64 + ch * 8);
    }
}

// ===========================================================================
// gemm_proj: z=0/1/2 -> Q/K/V, single fp16 in and out.
// ===========================================================================
__global__ __launch_bounds__(256, 2)
void gemm_proj(const __half* __restrict__ aQ, const __half* __restrict__ aK,
               const __half* __restrict__ aV,
               const __half* __restrict__ wq, const __half* __restrict__ wk,
               const __half* __restrict__ wv,
               __half* __restrict__ Qv, __half* __restrict__ Kv,
               __half* __restrict__ Vv)
{
    extern __shared__ char smc[];
    const uint32_t sb = smem_u32(smc);
    const int tid  = threadIdx.x;
    const int wid  = tid >> 5;
    const int lane = tid & 31;
    const int warp_m = wid & 1;
    const int warp_n = wid >> 1;
    const int m0 = blockIdx.y * 128;
    const int n0 = blockIdx.x * 128;
    const int z  = blockIdx.z;
    const int N  = D_DIM;

    const __half* Ab = ((z == 0) ? aQ : (z == 1) ? aK : aV) + (size_t)m0 * D_DIM;
    const __half* Bb = ((z == 0) ? wq : (z == 1) ? wk : wv) + (size_t)n0 * D_DIM;

    float acc[4][4][4];
#pragma unroll
    for (int mi = 0; mi < 4; mi++)
#pragma unroll
        for (int ni = 0; ni < 4; ni++)
#pragma unroll
            for (int q = 0; q < 4; q++) acc[mi][ni][q] = 0.f;

    const int lr  = lane & 15;
    const int lkb = (lane >> 4) << 4;

    gemm_produce(sb, 0, Ab, Bb, tid);
    cp_commit();

    for (int s = 0; s < STAGES; s++) {
        if (s + 1 < STAGES) {
            gemm_produce(sb, s + 1, Ab, Bb, tid);
            cp_commit();
            cp_wait1();
        } else {
            cp_wait0();
        }
        __syncthreads();
        gemm_stage_compute(sb + (s & 1) * GSTAGE, warp_m, warp_n, lr, lkb, acc);
        __syncthreads();
    }

    const int er = lane >> 2;
    const int ec = (lane & 3) * 2;
    __half* C = (z == 0) ? Qv : (z == 1) ? Kv : Vv;
#pragma unroll
    for (int mi = 0; mi < 4; mi++)
#pragma unroll
        for (int ni = 0; ni < 4; ni++) {
            const int r = m0 + warp_m * 64 + mi * 16 + er;
            const int c = n0 + warp_n * 32 + ni * 8 + ec;
            *(uint32_t*)(C + (size_t)r * N + c) =
                packh(acc[mi][ni][0], acc[mi][ni][1]);
            *(uint32_t*)(C + (size_t)(r + 8) * N + c) =
                packh(acc[mi][ni][2], acc[mi][ni][3]);
        }
}

// ===========================================================================
// gemm_out: out = X @ Wo^T (f32 out). X and Wo single fp16.
// ===========================================================================
__global__ __launch_bounds__(256, 2)
void gemm_out(const __half* __restrict__ Xv, const __half* __restrict__ wo,
              float* __restrict__ out)
{
    extern __shared__ char smc[];
    const uint32_t sb = smem_u32(smc);
    const int tid  = threadIdx.x;
    const int wid  = tid >> 5;
    const int lane = tid & 31;
    const int warp_m = wid & 1;
    const int warp_n = wid >> 1;
    const int m0 = blockIdx.y * 128;
    const int n0 = blockIdx.x * 128;
    const int N  = D_DIM;

    const __half* Ab = Xv + (size_t)m0 * D_DIM;
    const __half* Bb = wo + (size_t)n0 * D_DIM;

    float acc[4][4][4];
#pragma unroll
    for (int mi = 0; mi < 4; mi++)
#pragma unroll
        for (int ni = 0; ni < 4; ni++)
#pragma unroll
            for (int q = 0; q < 4; q++) acc[mi][ni][q] = 0.f;

    const int lr  = lane & 15;
    const int lkb = (lane >> 4) << 4;

    gemm_produce(sb, 0, Ab, Bb, tid);
    cp_commit();

    for (int s = 0; s < STAGES; s++) {
        if (s + 1 < STAGES) {
            gemm_produce(sb, s + 1, Ab, Bb, tid);
            cp_commit();
            cp_wait1();
        } else {
            cp_wait0();
        }
        __syncthreads();
        gemm_stage_compute(sb + (s & 1) * GSTAGE, warp_m, warp_n, lr, lkb, acc);
        __syncthreads();
    }

    const int er = lane >> 2;
    const int ec = (lane & 3) * 2;
#pragma unroll
    for (int mi = 0; mi < 4; mi++)
#pragma unroll
        for (int ni = 0; ni < 4; ni++) {
            const int r = m0 + warp_m * 64 + mi * 16 + er;
            const int c = n0 + warp_n * 32 + ni * 8 + ec;
            *(float2*)(out + (size_t)r * N + c) =
                make_float2(acc[mi][ni][0], acc[mi][ni][1]);
            *(float2*)(out + (size_t)(r + 8) * N + c) =
                make_float2(acc[mi][ni][2], acc[mi][ni][3]);
        }
}

// ===========================================================================
// Flash attention (causal). CTA = 128 q-rows x (b,h), 256 threads, 8 warps.
// Q, K, V, P single fp16; single fp16 X output. 2 CTAs/SM.
// ===========================================================================
constexpr int FQT  = 128 * SASB;           // 18432: single Q tile
constexpr int FKV0 = FQT;                  // 18432
constexpr int KVT  = 64 * SASB;            // 9216 per 64-row tile
constexpr int KVBUF = 2 * KVT;             // 18432 (K, V)
constexpr int FSM_TOTAL = FKV0 + 2 * KVBUF;  // 55296 (x2 CTAs = 108KB/SM)

__global__ __launch_bounds__(256, 2)
void flash_mma(const __half* __restrict__ Qv, const __half* __restrict__ Kv,
               const __half* __restrict__ Vv, __half* __restrict__ Xv)
{
    extern __shared__ char smc[];
    const uint32_t sb = smem_u32(smc);
    const int tid  = threadIdx.x;
    const int wid  = tid >> 5;
    const int lane = tid & 31;
    const int qb   = gridDim.x - 1 - blockIdx.x;   // longest blocks first
    const int h    = blockIdx.y;
    const int b    = blockIdx.z;

    const size_t head = (size_t)b * S_LEN * D_DIM + (size_t)h * DKH;
    const int prow = tid >> 3;
    const int pch  = tid & 7;

    { // Q tile (single): 4 cp.async per thread
#pragma unroll
        for (int i = 0; i < 4; i++) {
            const int row = (i << 5) | prow;
            const void* src = Qv + head + (size_t)(qb * 128 + row) * D_DIM + pch * 8;
            cpasync16(sb + row * SASB + pch * 16, src);
        }
    }

    const __half* kvb[2] = {Kv + head, Vv + head};
    auto produce_kv = [&](int kb) {
        const uint32_t bufb = sb + FKV0 + (kb & 1) * KVBUF;
#pragma unroll
        for (int i = 0; i < 4; i++) {
            const int t   = i >> 1;
            const int row = ((i & 1) << 5) | prow;
            const void* src = kvb[t] + (size_t)(kb * 64 + row) * D_DIM + pch * 8;
            cpasync16(bufb + t * KVT + row * SASB + pch * 16, src);
        }
    };

    produce_kv(0);
    cp_commit();

    float o[8][4];
    float m0r = -1e30f, m1r = -1e30f, l0r = 0.f, l1r = 0.f;
#pragma unroll
    for (int ni = 0; ni < 8; ni++)
#pragma unroll
        for (int q = 0; q < 4; q++) o[ni][q] = 0.f;

    const int lr  = lane & 15;
    const int lkb = (lane >> 4) << 4;
    const int kb_max = 2 * qb + 1;

    for (int kb = 0; kb <= kb_max; kb++) {
        if (kb < kb_max) {
            produce_kv(kb + 1);
            cp_commit();
            cp_wait1();
        } else {
            cp_wait0();
        }
        __syncthreads();

        const uint32_t kvbase = sb + FKV0 + (kb & 1) * KVBUF;

        // ---- QK^T ----
        float sc[8][4];
#pragma unroll
        for (int ni = 0; ni < 8; ni++)
#pragma unroll
            for (int q = 0; q < 4; q++) sc[ni][q] = 0.f;

#pragma unroll
        for (int ks = 0; ks < 4; ks++) {
            const uint32_t abyte = (wid * 16 + lr) * SASB + ks * 32 + lkb;
            uint32_t qh[4];
            ldmx4(qh, sb + abyte);
#pragma unroll
            for (int nb = 0; nb < 4; nb++) {
                const uint32_t bbyte = (nb * 16 + lr) * SASB + ks * 32 + lkb;
                uint32_t kh[4];
                ldmx4(kh, kvbase + bbyte);
                mma16816(sc[nb * 2],     qh, kh[0], kh[2]);
                mma16816(sc[nb * 2 + 1], qh, kh[1], kh[3]);
            }
        }

#pragma unroll
        for (int ni = 0; ni < 8; ni++)
#pragma unroll
            for (int q = 0; q < 4; q++) sc[ni][q] *= 0.125f;

        const int q0 = qb * 128 + wid * 16 + (lane >> 2);
        if (kb * 64 + 63 > qb * 128 + wid * 16) {
#pragma unroll
            for (int ni = 0; ni < 8; ni++) {
#pragma unroll
                for (int c = 0; c < 2; c++) {
                    const int col = kb * 64 + ni * 8 + (lane & 3) * 2 + c;
                    if (col > q0)     sc[ni][c]     = -1e30f;
                    if (col > q0 + 8) sc[ni][2 + c] = -1e30f;
                }
            }
        }

        float mx0 = -1e30f, mx1 = -1e30f;
#pragma unroll
        for (int ni = 0; ni < 8; ni++) {
            mx0 = fmaxf(mx0, fmaxf(sc[ni][0], sc[ni][1]));
            mx1 = fmaxf(mx1, fmaxf(sc[ni][2], sc[ni][3]));
        }
        mx0 = fmaxf(mx0, __shfl_xor_sync(0xffffffffu, mx0, 1));
        mx0 = fmaxf(mx0, __shfl_xor_sync(0xffffffffu, mx0, 2));
        mx1 = fmaxf(mx1, __shfl_xor_sync(0xffffffffu, mx1, 1));
        mx1 = fmaxf(mx1, __shfl_xor_sync(0xffffffffu, mx1, 2));

        const float mn0 = fmaxf(m0r, mx0);
        const float mn1 = fmaxf(m1r, mx1);
        const float al0 = __expf(m0r - mn0);
        const float al1 = __expf(m1r - mn1);
        m0r = mn0; m1r = mn1;

        float ls0 = 0.f, ls1 = 0.f;
#pragma unroll
        for (int ni = 0; ni < 8; ni++) {
            sc[ni][0] = __expf(sc[ni][0] - mn0); ls0 += sc[ni][0];
            sc[ni][1] = __expf(sc[ni][1] - mn0); ls0 += sc[ni][1];
            sc[ni][2] = __expf(sc[ni][2] - mn1); ls1 += sc[ni][2];
            sc[ni][3] = __expf(sc[ni][3] - mn1); ls1 += sc[ni][3];
        }
        ls0 += __shfl_xor_sync(0xffffffffu, ls0, 1);
        ls0 += __shfl_xor_sync(0xffffffffu, ls0, 2);
        ls1 += __shfl_xor_sync(0xffffffffu, ls1, 1);
        ls1 += __shfl_xor_sync(0xffffffffu, ls1, 2);
        l0r = l0r * al0 + ls0;
        l1r = l1r * al1 + ls1;
#pragma unroll
        for (int ni = 0; ni < 8; ni++) {
            o[ni][0] *= al0; o[ni][1] *= al0;
            o[ni][2] *= al1; o[ni][3] *= al1;
        }

        // ---- P.V ----
#pragma unroll
        for (int ks = 0; ks < 4; ks++) {
            uint32_t ph[4];
            ph[0] = packh(sc[2 * ks][0],     sc[2 * ks][1]);
            ph[1] = packh(sc[2 * ks][2],     sc[2 * ks][3]);
            ph[2] = packh(sc[2 * ks + 1][0], sc[2 * ks + 1][1]);
            ph[3] = packh(sc[2 * ks + 1][2], sc[2 * ks + 1][3]);
#pragma unroll
            for (int nt = 0; nt < 4; nt++) {
                const uint32_t vbyte =
                    (ks * 16 + ((lane >> 3) & 1) * 8 + (lane & 7)) * SASB +
                    nt * 32 + ((lane >> 4) << 4);
                uint32_t vh[4];
                ldmx4t(vh, kvbase + KVT + vbyte);
                mma16816(o[nt * 2],     ph, vh[0], vh[1]);
                mma16816(o[nt * 2 + 1], ph, vh[2], vh[3]);
            }
        }
        __syncthreads();
    }

    const float inv0 = 1.f / l0r;
    const float inv1 = 1.f / l1r;
    const int r0 = qb * 128 + wid * 16 + (lane >> 2);
    const int ec = (lane & 3) * 2;
#pragma unroll
    for (int ni = 0; ni < 8; ni++) {
        const size_t c = head + (size_t)ni * 8 + ec;
        *(uint32_t*)(Xv + c + (size_t)r0 * D_DIM) =
            packh(o[ni][0] * inv0, o[ni][1] * inv0);
        *(uint32_t*)(Xv + c + (size_t)(r0 + 8) * D_DIM) =
            packh(o[ni][2] * inv1, o[ni][3] * inv1);
    }
}

// ---------------------------------------------------------------------------
// launch
// ---------------------------------------------------------------------------
extern "C" void kernel_launch(void* const* d_in, const int* in_sizes, int n_in,
                              void* d_out, int out_size)
{
    const float* query = (const float*)d_in[0];
    const float* key   = (const float*)d_in[1];
    const float* value = (const float*)d_in[2];
    const float* Wq    = (const float*)d_in[3];
    const float* Wk    = (const float*)d_in[4];
    const float* Wv    = (const float*)d_in[5];
    const float* Wo    = (const float*)d_in[6];
    float* out = (float*)d_out;

    __half *aQ, *aK, *aV, *wq, *wk, *wv, *wo, *Qv, *Kv, *Vv, *Xv;
    cudaGetSymbolAddress((void**)&aQ, g_aQ); cudaGetSymbolAddress((void**)&aK, g_aK);
    cudaGetSymbolAddress((void**)&aV, g_aV);
    cudaGetSymbolAddress((void**)&wq, g_wq); cudaGetSymbolAddress((void**)&wk, g_wk);
    cudaGetSymbolAddress((void**)&wv, g_wv); cudaGetSymbolAddress((void**)&wo, g_wo);
    cudaGetSymbolAddress((void**)&Qv, g_Qv); cudaGetSymbolAddress((void**)&Kv, g_Kv);
    cudaGetSymbolAddress((void**)&Vv, g_Vv); cudaGetSymbolAddress((void**)&Xv, g_Xv);

    cudaFuncSetAttribute(gemm_proj, cudaFuncAttributeMaxDynamicSharedMemorySize,
                         SM_GEMM_TOTAL);
    cudaFuncSetAttribute(gemm_out, cudaFuncAttributeMaxDynamicSharedMemorySize,
                         SM_GEMM_TOTAL);
    cudaFuncSetAttribute(flash_mma, cudaFuncAttributeMaxDynamicSharedMemorySize,
                         FSM_TOTAL);

    dim3 cgrid(128, 1, 7);
    convert_all<<<cgrid, 256>>>((const float4*)query, (const float4*)key,
                                (const float4*)value, (const float4*)Wq,
                                (const float4*)Wk, (const float4*)Wv,
                                (const float4*)Wo,
                                (uint2*)aQ, (uint2*)aK, (uint2*)aV,
                                (uint2*)wq, (uint2*)wk, (uint2*)wv, (uint2*)wo);

    dim3 pgrid(D_DIM / 128, MTOT / 128, 3);   // (8, 32, 3)
    gemm_proj<<<pgrid, 256, SM_GEMM_TOTAL>>>(aQ, aK, aV, wq, wk, wv, Qv, Kv, Vv);

    dim3 fgrid(S_LEN / 128, H_NUM, B_SZ);     // (16, 16, 2)
    flash_mma<<<fgrid, 256, FSM_TOTAL>>>(Qv, Kv, Vv, Xv);

    dim3 ogrid(D_DIM / 128, MTOT / 128);      // (8, 32)
    gemm_out<<<ogrid, 256, SM_GEMM_TOTAL>>>(Xv, wo, out);
}